// round 1
// baseline (speedup 1.0000x reference)
#include <cuda_runtime.h>
#include <math.h>

// Problem constants (fixed by the dataset)
#define NODES 100000
#define EDGES 1600000
#define GRAPHS 256
#define INF 128
#define HF 64

// ---------------- scratch (static device globals; no allocation) -------------
__device__ int   g_cnt_out[NODES];
__device__ int   g_cnt_in[NODES];
__device__ float g_ns[NODES];
__device__ float g_nd[NODES];
__device__ int   g_rowptr[NODES + 1];
__device__ int   g_cursor[NODES];
__device__ int   g_csr_src[EDGES];
__device__ float g_csr_w[EDGES];
__device__ float g_t[NODES * HF];    // per-layer GEMM output (pre-scatter)
__device__ float g_agg[NODES * HF];  // per-layer aggregation result

// ---------------- init: zero degree counters ---------------------------------
__global__ void zero_counts_kernel() {
    int i = blockIdx.x * blockDim.x + threadIdx.x;
    if (i < NODES) { g_cnt_out[i] = 0; g_cnt_in[i] = 0; }
}

// ---------------- degree histogram -------------------------------------------
__global__ void degree_kernel(const int* __restrict__ src, const int* __restrict__ dst) {
    int e = blockIdx.x * blockDim.x + threadIdx.x;
    if (e < EDGES) {
        atomicAdd(&g_cnt_out[src[e]], 1);
        atomicAdd(&g_cnt_in[dst[e]], 1);
    }
}

// ---------------- norms -------------------------------------------------------
__global__ void norm_kernel() {
    int i = blockIdx.x * blockDim.x + threadIdx.x;
    if (i < NODES) {
        g_ns[i] = rsqrtf(fmaxf((float)g_cnt_out[i], 1.0f));
        g_nd[i] = rsqrtf(fmaxf((float)g_cnt_in[i], 1.0f));
    }
}

// ---------------- single-block exclusive scan of deg_in → rowptr/cursor -------
__global__ void scan_kernel() {
    const int T = 1024;
    const int CH = (NODES + T - 1) / T;  // 98
    int t = threadIdx.x;
    int base = t * CH;
    int s = 0;
    for (int i = 0; i < CH; i++) {
        int idx = base + i;
        if (idx < NODES) s += g_cnt_in[idx];
    }
    __shared__ int ss[T];
    ss[t] = s;
    __syncthreads();
    for (int d = 1; d < T; d <<= 1) {
        int other = (t >= d) ? ss[t - d] : 0;
        __syncthreads();
        ss[t] += other;
        __syncthreads();
    }
    int off = ss[t] - s;  // exclusive prefix
    for (int i = 0; i < CH; i++) {
        int idx = base + i;
        if (idx < NODES) {
            g_rowptr[idx] = off;
            g_cursor[idx] = off;
            off += g_cnt_in[idx];
        }
    }
    if (t == T - 1) g_rowptr[NODES] = off;
}

// ---------------- CSR fill (by dst) -------------------------------------------
__global__ void csr_fill_kernel(const int* __restrict__ src, const int* __restrict__ dst,
                                const float* __restrict__ ew) {
    int e = blockIdx.x * blockDim.x + threadIdx.x;
    if (e < EDGES) {
        int d = dst[e];
        int p = atomicAdd(&g_cursor[d], 1);
        g_csr_src[p] = src[e];
        g_csr_w[p] = ew[e];
    }
}

// ---------------- GEMM: t = f(A) @ W  (64-col output) --------------------------
// MODE 0: f(A)[r,k] = A[r,k] * ns[r]                     (layer 1, K may be 128)
// MODE 1: f(A)[r,k] = relu(A[r,k]*nd[r] + bprev[k]) * ns[r]  (layers 2/3, K=64)
// block: 64 threads, tile 64 rows x 64 cols; thread: 4 rows x 16 cols.
template <int K, int MODE>
__global__ void gemm_kernel(const float* __restrict__ A, const float* __restrict__ W,
                            const float* __restrict__ bprev, float* __restrict__ out) {
    __shared__ float sW[64][64];   // [k-chunk][col]
    __shared__ float sA[64][65];   // [row][k-chunk] (+pad)
    const int tid = threadIdx.x;       // 0..63
    const int row0 = blockIdx.x * 64;
    const int cg = tid & 3;            // col group: cols cg*16 .. cg*16+15
    const int rg = tid >> 2;           // row group: rows rg*4 .. rg*4+3

    float acc[4][16];
#pragma unroll
    for (int i = 0; i < 4; i++)
#pragma unroll
        for (int j = 0; j < 16; j++) acc[i][j] = 0.0f;

    for (int chunk = 0; chunk < K; chunk += 64) {
        // load W chunk: 64 k-rows x 64 cols, coalesced
#pragma unroll
        for (int it = 0; it < 64; it++) {
            sW[it][tid] = W[(chunk + it) * HF + tid];
        }
        // load + transform A chunk: thread owns column k = tid for 64 rows
        float bk = 0.0f;
        if (MODE == 1) bk = bprev[chunk + tid];
#pragma unroll 4
        for (int it = 0; it < 64; it++) {
            int row = row0 + it;
            float v = 0.0f;
            if (row < NODES) {
                v = A[(long)row * K + chunk + tid];
                if (MODE == 1) v = fmaxf(fmaf(v, g_nd[row], bk), 0.0f);
                v *= g_ns[row];
            }
            sA[it][tid] = v;
        }
        __syncthreads();

#pragma unroll 4
        for (int kk = 0; kk < 64; kk++) {
            float a0 = sA[rg * 4 + 0][kk];
            float a1 = sA[rg * 4 + 1][kk];
            float a2 = sA[rg * 4 + 2][kk];
            float a3 = sA[rg * 4 + 3][kk];
            const float4 w0 = *(const float4*)&sW[kk][cg * 16 + 0];
            const float4 w1 = *(const float4*)&sW[kk][cg * 16 + 4];
            const float4 w2 = *(const float4*)&sW[kk][cg * 16 + 8];
            const float4 w3 = *(const float4*)&sW[kk][cg * 16 + 12];
#define FMA_ROW(i, a)                                                   \
            acc[i][0]  = fmaf(a, w0.x, acc[i][0]);                      \
            acc[i][1]  = fmaf(a, w0.y, acc[i][1]);                      \
            acc[i][2]  = fmaf(a, w0.z, acc[i][2]);                      \
            acc[i][3]  = fmaf(a, w0.w, acc[i][3]);                      \
            acc[i][4]  = fmaf(a, w1.x, acc[i][4]);                      \
            acc[i][5]  = fmaf(a, w1.y, acc[i][5]);                      \
            acc[i][6]  = fmaf(a, w1.z, acc[i][6]);                      \
            acc[i][7]  = fmaf(a, w1.w, acc[i][7]);                      \
            acc[i][8]  = fmaf(a, w2.x, acc[i][8]);                      \
            acc[i][9]  = fmaf(a, w2.y, acc[i][9]);                      \
            acc[i][10] = fmaf(a, w2.z, acc[i][10]);                     \
            acc[i][11] = fmaf(a, w2.w, acc[i][11]);                     \
            acc[i][12] = fmaf(a, w3.x, acc[i][12]);                     \
            acc[i][13] = fmaf(a, w3.y, acc[i][13]);                     \
            acc[i][14] = fmaf(a, w3.z, acc[i][14]);                     \
            acc[i][15] = fmaf(a, w3.w, acc[i][15]);
            FMA_ROW(0, a0)
            FMA_ROW(1, a1)
            FMA_ROW(2, a2)
            FMA_ROW(3, a3)
#undef FMA_ROW
        }
        __syncthreads();
    }

#pragma unroll
    for (int i = 0; i < 4; i++) {
        int row = row0 + rg * 4 + i;
        if (row < NODES) {
            float* o = &out[(long)row * HF + cg * 16];
#pragma unroll
            for (int q = 0; q < 4; q++) {
                float4 v = make_float4(acc[i][q * 4 + 0], acc[i][q * 4 + 1],
                                       acc[i][q * 4 + 2], acc[i][q * 4 + 3]);
                *(float4*)&o[q * 4] = v;
            }
        }
    }
}

// ---------------- CSR gather aggregation: agg[d] = sum_e w_e * t[src_e] -------
// warp per dst node; lanes cover 64 features (2 per lane).
__global__ void agg_kernel(const float* __restrict__ t, float* __restrict__ agg) {
    int node = blockIdx.x * 8 + (threadIdx.x >> 5);
    if (node >= NODES) return;
    int lane = threadIdx.x & 31;
    int beg = g_rowptr[node];
    int end = g_rowptr[node + 1];
    float a0 = 0.0f, a1 = 0.0f;
    int j = beg;
    for (; j + 1 < end; j += 2) {
        int s0 = g_csr_src[j];
        int s1 = g_csr_src[j + 1];
        float w0 = g_csr_w[j];
        float w1 = g_csr_w[j + 1];
        float v00 = t[(long)s0 * HF + lane];
        float v01 = t[(long)s0 * HF + 32 + lane];
        float v10 = t[(long)s1 * HF + lane];
        float v11 = t[(long)s1 * HF + 32 + lane];
        a0 = fmaf(v00, w0, a0);
        a1 = fmaf(v01, w0, a1);
        a0 = fmaf(v10, w1, a0);
        a1 = fmaf(v11, w1, a1);
    }
    if (j < end) {
        int s0 = g_csr_src[j];
        float w0 = g_csr_w[j];
        a0 = fmaf(t[(long)s0 * HF + lane], w0, a0);
        a1 = fmaf(t[(long)s0 * HF + 32 + lane], w0, a1);
    }
    agg[(long)node * HF + lane] = a0;
    agg[(long)node * HF + 32 + lane] = a1;
}

// ---------------- pool (mean per graph) + MLP head + sigmoid ------------------
__device__ __forceinline__ int lower_bound_dev(const int* __restrict__ a, int n, int key) {
    int lo = 0, hi = n;
    while (lo < hi) {
        int mid = (lo + hi) >> 1;
        if (a[mid] < key) lo = mid + 1; else hi = mid;
    }
    return lo;
}

__global__ void pool_mlp_kernel(const float* __restrict__ agg, const float* __restrict__ b3,
                                const int* __restrict__ gid,
                                const float* __restrict__ Dw1, const float* __restrict__ Db1,
                                const float* __restrict__ Dw2, const float* __restrict__ Db2,
                                const float* __restrict__ Dw3, const float* __restrict__ Db3,
                                float* __restrict__ out) {
    int g = blockIdx.x;
    int t = threadIdx.x;  // 64 threads
    int start = lower_bound_dev(gid, NODES, g);
    int end = lower_bound_dev(gid, NODES, g + 1);

    float b = b3[t];
    float sum = 0.0f;
    for (int n = start; n < end; n++) {
        float v = fmaf(agg[(long)n * HF + t], g_nd[n], b);
        sum += fmaxf(v, 0.0f);
    }
    float cnt = fmaxf((float)(end - start), 1.0f);

    __shared__ float pooled[64];
    __shared__ float h1[16];
    __shared__ float h2[8];
    pooled[t] = sum / cnt;
    __syncthreads();

    if (t < 16) {
        float s = Db1[t];
#pragma unroll
        for (int k = 0; k < 64; k++) s = fmaf(pooled[k], Dw1[k * 16 + t], s);
        h1[t] = fmaxf(s, 0.0f);
    }
    __syncthreads();
    if (t < 8) {
        float s = Db2[t];
#pragma unroll
        for (int k = 0; k < 16; k++) s = fmaf(h1[k], Dw2[k * 8 + t], s);
        h2[t] = fmaxf(s, 0.0f);
    }
    __syncthreads();
    if (t == 0) {
        float s = Db3[0];
#pragma unroll
        for (int k = 0; k < 8; k++) s = fmaf(h2[k], Dw3[k], s);
        out[g] = 1.0f / (1.0f + expf(-s));
    }
}

// ---------------- launch ------------------------------------------------------
extern "C" void kernel_launch(void* const* d_in, const int* in_sizes, int n_in,
                              void* d_out, int out_size) {
    const float* x   = (const float*)d_in[0];
    const int*   src = (const int*)d_in[1];
    const int*   dst = (const int*)d_in[2];
    const float* ew  = (const float*)d_in[3];
    const int*   gid = (const int*)d_in[4];
    const float* W1  = (const float*)d_in[5];
    const float* b1  = (const float*)d_in[6];
    const float* W2  = (const float*)d_in[7];
    const float* b2  = (const float*)d_in[8];
    const float* W3  = (const float*)d_in[9];
    const float* b3  = (const float*)d_in[10];
    const float* Dw1 = (const float*)d_in[11];
    const float* Db1 = (const float*)d_in[12];
    const float* Dw2 = (const float*)d_in[13];
    const float* Db2 = (const float*)d_in[14];
    const float* Dw3 = (const float*)d_in[15];
    const float* Db3 = (const float*)d_in[16];
    float* out = (float*)d_out;

    float* t_ptr;   cudaGetSymbolAddress((void**)&t_ptr, g_t);
    float* agg_ptr; cudaGetSymbolAddress((void**)&agg_ptr, g_agg);

    const int NB = (NODES + 255) / 256;
    const int EB = (EDGES + 255) / 256;
    const int GB = (NODES + 63) / 64;   // gemm blocks
    const int AB = (NODES + 7) / 8;     // agg blocks (8 warps each)

    // graph preprocessing
    zero_counts_kernel<<<NB, 256>>>();
    degree_kernel<<<EB, 256>>>(src, dst);
    norm_kernel<<<NB, 256>>>();
    scan_kernel<<<1, 1024>>>();
    csr_fill_kernel<<<EB, 256>>>(src, dst, ew);

    // layer 1: t = (x*ns)@W1 ; agg = scatter(t)
    gemm_kernel<INF, 0><<<GB, 64>>>(x, W1, nullptr, t_ptr);
    agg_kernel<<<AB, 256>>>(t_ptr, agg_ptr);

    // layer 2: t = (relu(agg*nd+b1)*ns)@W2 ; agg = scatter(t)
    gemm_kernel<HF, 1><<<GB, 64>>>(agg_ptr, W2, b1, t_ptr);
    agg_kernel<<<AB, 256>>>(t_ptr, agg_ptr);

    // layer 3: t = (relu(agg*nd+b2)*ns)@W3 ; agg = scatter(t)
    gemm_kernel<HF, 1><<<GB, 64>>>(agg_ptr, W3, b2, t_ptr);
    agg_kernel<<<AB, 256>>>(t_ptr, agg_ptr);

    // pool + MLP + sigmoid
    pool_mlp_kernel<<<GRAPHS, 64>>>(agg_ptr, b3, gid, Dw1, Db1, Dw2, Db2, Dw3, Db3, out);
}

// round 2
// speedup vs baseline: 1.3822x; 1.3822x over previous
#include <cuda_runtime.h>
#include <math.h>

// Problem constants (fixed by the dataset)
#define NODES 100000
#define EDGES 1600000
#define GRAPHS 256
#define INF 128
#define HF 64
#define SCAN_BLK 256
#define NBLK ((NODES + SCAN_BLK - 1) / SCAN_BLK)   // 391

// ---------------- scratch (static device globals; no allocation) -------------
__device__ int   g_cnt_out[NODES];
__device__ int   g_cnt_in[NODES];
__device__ float g_ns[NODES];
__device__ float g_nd[NODES];
__device__ int   g_rowptr[NODES + 1];
__device__ int   g_cursor[NODES];
__device__ int   g_csr_src[EDGES];
__device__ float g_csr_w[EDGES];
__device__ int   g_blockSums[NBLK];
__device__ int   g_blockOff[NBLK];
__device__ float g_t[NODES * HF];    // per-layer GEMM output (pre-scatter)
__device__ float g_agg[NODES * HF];  // per-layer aggregation result

// ---------------- init: zero degree counters ---------------------------------
__global__ void zero_counts_kernel() {
    int i = blockIdx.x * blockDim.x + threadIdx.x;
    if (i < NODES) { g_cnt_out[i] = 0; g_cnt_in[i] = 0; }
}

// ---------------- degree histogram -------------------------------------------
__global__ void degree_kernel(const int* __restrict__ src, const int* __restrict__ dst) {
    int e = blockIdx.x * blockDim.x + threadIdx.x;
    if (e < EDGES) {
        atomicAdd(&g_cnt_out[src[e]], 1);
        atomicAdd(&g_cnt_in[dst[e]], 1);
    }
}

// ---------------- 3-phase parallel scan of deg_in -----------------------------
// phase 1: per-block reduce (coalesced)
__global__ void scan1_kernel() {
    int i = blockIdx.x * SCAN_BLK + threadIdx.x;
    int c = (i < NODES) ? g_cnt_in[i] : 0;
#pragma unroll
    for (int d = 16; d; d >>= 1) c += __shfl_down_sync(0xffffffffu, c, d);
    __shared__ int w[SCAN_BLK / 32];
    if ((threadIdx.x & 31) == 0) w[threadIdx.x >> 5] = c;
    __syncthreads();
    if (threadIdx.x < SCAN_BLK / 32) {
        int s = w[threadIdx.x];
#pragma unroll
        for (int d = SCAN_BLK / 64; d; d >>= 1) s += __shfl_down_sync(0xffu, s, d);
        if (threadIdx.x == 0) g_blockSums[blockIdx.x] = s;
    }
}

// phase 2: single-block scan of the 391 block sums
__global__ void scan2_kernel() {
    __shared__ int ss[512];
    int t = threadIdx.x;
    int v = (t < NBLK) ? g_blockSums[t] : 0;
    ss[t] = v;
    __syncthreads();
    for (int d = 1; d < 512; d <<= 1) {
        int o = (t >= d) ? ss[t - d] : 0;
        __syncthreads();
        ss[t] += o;
        __syncthreads();
    }
    if (t < NBLK) g_blockOff[t] = ss[t] - v;  // exclusive
}

// phase 3: block-local exclusive scan + offset -> rowptr/cursor; fused norms
__global__ void scan3_kernel() {
    int i = blockIdx.x * SCAN_BLK + threadIdx.x;
    int c = (i < NODES) ? g_cnt_in[i] : 0;
    int lane = threadIdx.x & 31, wid = threadIdx.x >> 5;
    int v = c;
#pragma unroll
    for (int d = 1; d < 32; d <<= 1) {
        int n = __shfl_up_sync(0xffffffffu, v, d);
        if (lane >= d) v += n;
    }
    __shared__ int wsum[SCAN_BLK / 32];
    if (lane == 31) wsum[wid] = v;
    __syncthreads();
    if (threadIdx.x < SCAN_BLK / 32) {
        int s = wsum[threadIdx.x];
#pragma unroll
        for (int d = 1; d < SCAN_BLK / 32; d <<= 1) {
            int n = __shfl_up_sync(0xffu, s, d);
            if ((int)threadIdx.x >= d) s += n;
        }
        wsum[threadIdx.x] = s;
    }
    __syncthreads();
    int excl = v - c + (wid > 0 ? wsum[wid - 1] : 0) + g_blockOff[blockIdx.x];
    if (i < NODES) {
        g_rowptr[i] = excl;
        g_cursor[i] = excl;
        g_ns[i] = rsqrtf(fmaxf((float)g_cnt_out[i], 1.0f));
        g_nd[i] = rsqrtf(fmaxf((float)c, 1.0f));
    }
    if (blockIdx.x == 0 && threadIdx.x == 0) g_rowptr[NODES] = EDGES;
}

// ---------------- CSR fill (by dst) -------------------------------------------
__global__ void csr_fill_kernel(const int* __restrict__ src, const int* __restrict__ dst,
                                const float* __restrict__ ew) {
    int e = blockIdx.x * blockDim.x + threadIdx.x;
    if (e < EDGES) {
        int d = dst[e];
        int p = atomicAdd(&g_cursor[d], 1);
        g_csr_src[p] = src[e];
        g_csr_w[p] = ew[e];
    }
}

// ---------------- GEMM: t = f(A) @ W  (64-col output) --------------------------
// MODE 0: f(A)[r,k] = A[r,k] * ns[r]                     (layer 1, K may be 128)
// MODE 1: f(A)[r,k] = relu(A[r,k]*nd[r] + bprev[k]) * ns[r]  (layers 2/3, K=64)
// block: 64 threads, tile 64 rows x 64 cols; thread: 4 rows x 16 cols.
template <int K, int MODE>
__global__ void gemm_kernel(const float* __restrict__ A, const float* __restrict__ W,
                            const float* __restrict__ bprev, float* __restrict__ out) {
    __shared__ float sW[64][64];   // [k-chunk][col]
    __shared__ float sA[64][65];   // [row][k-chunk] (+pad)
    const int tid = threadIdx.x;       // 0..63
    const int row0 = blockIdx.x * 64;
    const int cg = tid & 3;            // col group: cols cg*16 .. cg*16+15
    const int rg = tid >> 2;           // row group: rows rg*4 .. rg*4+3

    float acc[4][16];
#pragma unroll
    for (int i = 0; i < 4; i++)
#pragma unroll
        for (int j = 0; j < 16; j++) acc[i][j] = 0.0f;

    for (int chunk = 0; chunk < K; chunk += 64) {
        // load W chunk: 64 k-rows x 64 cols, coalesced
#pragma unroll
        for (int it = 0; it < 64; it++) {
            sW[it][tid] = W[(chunk + it) * HF + tid];
        }
        // load + transform A chunk: thread owns column k = tid for 64 rows
        float bk = 0.0f;
        if (MODE == 1) bk = bprev[chunk + tid];
#pragma unroll 4
        for (int it = 0; it < 64; it++) {
            int row = row0 + it;
            float v = 0.0f;
            if (row < NODES) {
                v = A[(long)row * K + chunk + tid];
                if (MODE == 1) v = fmaxf(fmaf(v, g_nd[row], bk), 0.0f);
                v *= g_ns[row];
            }
            sA[it][tid] = v;
        }
        __syncthreads();

#pragma unroll 4
        for (int kk = 0; kk < 64; kk++) {
            float a0 = sA[rg * 4 + 0][kk];
            float a1 = sA[rg * 4 + 1][kk];
            float a2 = sA[rg * 4 + 2][kk];
            float a3 = sA[rg * 4 + 3][kk];
            const float4 w0 = *(const float4*)&sW[kk][cg * 16 + 0];
            const float4 w1 = *(const float4*)&sW[kk][cg * 16 + 4];
            const float4 w2 = *(const float4*)&sW[kk][cg * 16 + 8];
            const float4 w3 = *(const float4*)&sW[kk][cg * 16 + 12];
#define FMA_ROW(i, a)                                                   \
            acc[i][0]  = fmaf(a, w0.x, acc[i][0]);                      \
            acc[i][1]  = fmaf(a, w0.y, acc[i][1]);                      \
            acc[i][2]  = fmaf(a, w0.z, acc[i][2]);                      \
            acc[i][3]  = fmaf(a, w0.w, acc[i][3]);                      \
            acc[i][4]  = fmaf(a, w1.x, acc[i][4]);                      \
            acc[i][5]  = fmaf(a, w1.y, acc[i][5]);                      \
            acc[i][6]  = fmaf(a, w1.z, acc[i][6]);                      \
            acc[i][7]  = fmaf(a, w1.w, acc[i][7]);                      \
            acc[i][8]  = fmaf(a, w2.x, acc[i][8]);                      \
            acc[i][9]  = fmaf(a, w2.y, acc[i][9]);                      \
            acc[i][10] = fmaf(a, w2.z, acc[i][10]);                     \
            acc[i][11] = fmaf(a, w2.w, acc[i][11]);                     \
            acc[i][12] = fmaf(a, w3.x, acc[i][12]);                     \
            acc[i][13] = fmaf(a, w3.y, acc[i][13]);                     \
            acc[i][14] = fmaf(a, w3.z, acc[i][14]);                     \
            acc[i][15] = fmaf(a, w3.w, acc[i][15]);
            FMA_ROW(0, a0)
            FMA_ROW(1, a1)
            FMA_ROW(2, a2)
            FMA_ROW(3, a3)
#undef FMA_ROW
        }
        __syncthreads();
    }

#pragma unroll
    for (int i = 0; i < 4; i++) {
        int row = row0 + rg * 4 + i;
        if (row < NODES) {
            float* o = &out[(long)row * HF + cg * 16];
#pragma unroll
            for (int q = 0; q < 4; q++) {
                float4 v = make_float4(acc[i][q * 4 + 0], acc[i][q * 4 + 1],
                                       acc[i][q * 4 + 2], acc[i][q * 4 + 3]);
                *(float4*)&o[q * 4] = v;
            }
        }
    }
}

// ---------------- CSR gather aggregation: agg[d] = sum_e w_e * t[src_e] -------
// warp per dst node; lanes cover 64 features (2 per lane).
__global__ void agg_kernel(const float* __restrict__ t, float* __restrict__ agg) {
    int node = blockIdx.x * 8 + (threadIdx.x >> 5);
    if (node >= NODES) return;
    int lane = threadIdx.x & 31;
    int beg = g_rowptr[node];
    int end = g_rowptr[node + 1];
    float a0 = 0.0f, a1 = 0.0f;
    int j = beg;
    for (; j + 1 < end; j += 2) {
        int s0 = g_csr_src[j];
        int s1 = g_csr_src[j + 1];
        float w0 = g_csr_w[j];
        float w1 = g_csr_w[j + 1];
        float v00 = t[(long)s0 * HF + lane];
        float v01 = t[(long)s0 * HF + 32 + lane];
        float v10 = t[(long)s1 * HF + lane];
        float v11 = t[(long)s1 * HF + 32 + lane];
        a0 = fmaf(v00, w0, a0);
        a1 = fmaf(v01, w0, a1);
        a0 = fmaf(v10, w1, a0);
        a1 = fmaf(v11, w1, a1);
    }
    if (j < end) {
        int s0 = g_csr_src[j];
        float w0 = g_csr_w[j];
        a0 = fmaf(t[(long)s0 * HF + lane], w0, a0);
        a1 = fmaf(t[(long)s0 * HF + 32 + lane], w0, a1);
    }
    agg[(long)node * HF + lane] = a0;
    agg[(long)node * HF + 32 + lane] = a1;
}

// ---------------- pool (mean per graph) + MLP head + sigmoid ------------------
__device__ __forceinline__ int lower_bound_dev(const int* __restrict__ a, int n, int key) {
    int lo = 0, hi = n;
    while (lo < hi) {
        int mid = (lo + hi) >> 1;
        if (a[mid] < key) lo = mid + 1; else hi = mid;
    }
    return lo;
}

__global__ void pool_mlp_kernel(const float* __restrict__ agg, const float* __restrict__ b3,
                                const int* __restrict__ gid,
                                const float* __restrict__ Dw1, const float* __restrict__ Db1,
                                const float* __restrict__ Dw2, const float* __restrict__ Db2,
                                const float* __restrict__ Dw3, const float* __restrict__ Db3,
                                float* __restrict__ out) {
    int g = blockIdx.x;
    int t = threadIdx.x;  // 64 threads
    int start = lower_bound_dev(gid, NODES, g);
    int end = lower_bound_dev(gid, NODES, g + 1);

    float b = b3[t];
    float sum = 0.0f;
    for (int n = start; n < end; n++) {
        float v = fmaf(agg[(long)n * HF + t], g_nd[n], b);
        sum += fmaxf(v, 0.0f);
    }
    float cnt = fmaxf((float)(end - start), 1.0f);

    __shared__ float pooled[64];
    __shared__ float h1[16];
    __shared__ float h2[8];
    pooled[t] = sum / cnt;
    __syncthreads();

    if (t < 16) {
        float s = Db1[t];
#pragma unroll
        for (int k = 0; k < 64; k++) s = fmaf(pooled[k], Dw1[k * 16 + t], s);
        h1[t] = fmaxf(s, 0.0f);
    }
    __syncthreads();
    if (t < 8) {
        float s = Db2[t];
#pragma unroll
        for (int k = 0; k < 16; k++) s = fmaf(h1[k], Dw2[k * 8 + t], s);
        h2[t] = fmaxf(s, 0.0f);
    }
    __syncthreads();
    if (t == 0) {
        float s = Db3[0];
#pragma unroll
        for (int k = 0; k < 8; k++) s = fmaf(h2[k], Dw3[k], s);
        out[g] = 1.0f / (1.0f + expf(-s));
    }
}

// ---------------- launch ------------------------------------------------------
extern "C" void kernel_launch(void* const* d_in, const int* in_sizes, int n_in,
                              void* d_out, int out_size) {
    const float* x   = (const float*)d_in[0];
    const int*   src = (const int*)d_in[1];
    const int*   dst = (const int*)d_in[2];
    const float* ew  = (const float*)d_in[3];
    const int*   gid = (const int*)d_in[4];
    const float* W1  = (const float*)d_in[5];
    const float* b1  = (const float*)d_in[6];
    const float* W2  = (const float*)d_in[7];
    const float* b2  = (const float*)d_in[8];
    const float* W3  = (const float*)d_in[9];
    const float* b3  = (const float*)d_in[10];
    const float* Dw1 = (const float*)d_in[11];
    const float* Db1 = (const float*)d_in[12];
    const float* Dw2 = (const float*)d_in[13];
    const float* Db2 = (const float*)d_in[14];
    const float* Dw3 = (const float*)d_in[15];
    const float* Db3 = (const float*)d_in[16];
    float* out = (float*)d_out;

    float* t_ptr;   cudaGetSymbolAddress((void**)&t_ptr, g_t);
    float* agg_ptr; cudaGetSymbolAddress((void**)&agg_ptr, g_agg);

    const int NB = (NODES + 255) / 256;
    const int EB = (EDGES + 255) / 256;
    const int GB = (NODES + 63) / 64;   // gemm blocks
    const int AB = (NODES + 7) / 8;     // agg blocks (8 warps each)

    // graph preprocessing
    zero_counts_kernel<<<NB, 256>>>();
    degree_kernel<<<EB, 256>>>(src, dst);
    scan1_kernel<<<NBLK, SCAN_BLK>>>();
    scan2_kernel<<<1, 512>>>();
    scan3_kernel<<<NBLK, SCAN_BLK>>>();
    csr_fill_kernel<<<EB, 256>>>(src, dst, ew);

    // layer 1: t = (x*ns)@W1 ; agg = scatter(t)
    gemm_kernel<INF, 0><<<GB, 64>>>(x, W1, nullptr, t_ptr);
    agg_kernel<<<AB, 256>>>(t_ptr, agg_ptr);

    // layer 2: t = (relu(agg*nd+b1)*ns)@W2 ; agg = scatter(t)
    gemm_kernel<HF, 1><<<GB, 64>>>(agg_ptr, W2, b1, t_ptr);
    agg_kernel<<<AB, 256>>>(t_ptr, agg_ptr);

    // layer 3: t = (relu(agg*nd+b2)*ns)@W3 ; agg = scatter(t)
    gemm_kernel<HF, 1><<<GB, 64>>>(agg_ptr, W3, b2, t_ptr);
    agg_kernel<<<AB, 256>>>(t_ptr, agg_ptr);

    // pool + MLP + sigmoid
    pool_mlp_kernel<<<GRAPHS, 64>>>(agg_ptr, b3, gid, Dw1, Db1, Dw2, Db2, Dw3, Db3, out);
}

// round 5
// speedup vs baseline: 1.4112x; 1.0210x over previous
#include <cuda_runtime.h>
#include <math.h>

// Problem constants (fixed by the dataset)
#define NODES 100000
#define EDGES 1600000
#define GRAPHS 256
#define INF 128
#define HF 64
#define SCAN_BLK 256
#define NBLK ((NODES + SCAN_BLK - 1) / SCAN_BLK)   // 391

// ---------------- scratch (static device globals; no allocation) -------------
__device__ int   g_cnt_out[NODES];
__device__ int   g_cnt_in[NODES];
__device__ float g_ns[NODES];
__device__ float g_nd[NODES];
__device__ int   g_rowptr[NODES + 1];
__device__ int   g_cursor[NODES];
__device__ int   g_csr_src[EDGES];
__device__ float g_csr_w[EDGES];
__device__ int   g_blockSums[NBLK];
__device__ int   g_blockOff[NBLK];
__device__ float g_t[NODES * HF];    // per-layer GEMM output (pre-scatter)
__device__ float g_agg[NODES * HF];  // per-layer aggregation result

// ---------------- init: zero degree counters ---------------------------------
__global__ void zero_counts_kernel() {
    int i = blockIdx.x * blockDim.x + threadIdx.x;
    if (i < NODES) { g_cnt_out[i] = 0; g_cnt_in[i] = 0; }
}

// ---------------- degree histogram -------------------------------------------
__global__ void degree_kernel(const int* __restrict__ src, const int* __restrict__ dst) {
    int e = blockIdx.x * blockDim.x + threadIdx.x;
    if (e < EDGES) {
        atomicAdd(&g_cnt_out[src[e]], 1);
        atomicAdd(&g_cnt_in[dst[e]], 1);
    }
}

// ---------------- 3-phase parallel scan of deg_in -----------------------------
__global__ void scan1_kernel() {
    int i = blockIdx.x * SCAN_BLK + threadIdx.x;
    int c = (i < NODES) ? g_cnt_in[i] : 0;
#pragma unroll
    for (int d = 16; d; d >>= 1) c += __shfl_down_sync(0xffffffffu, c, d);
    __shared__ int w[SCAN_BLK / 32];
    if ((threadIdx.x & 31) == 0) w[threadIdx.x >> 5] = c;
    __syncthreads();
    if (threadIdx.x < SCAN_BLK / 32) {
        int s = w[threadIdx.x];
#pragma unroll
        for (int d = SCAN_BLK / 64; d; d >>= 1) s += __shfl_down_sync(0xffu, s, d);
        if (threadIdx.x == 0) g_blockSums[blockIdx.x] = s;
    }
}

__global__ void scan2_kernel() {
    __shared__ int ss[512];
    int t = threadIdx.x;
    int v = (t < NBLK) ? g_blockSums[t] : 0;
    ss[t] = v;
    __syncthreads();
    for (int d = 1; d < 512; d <<= 1) {
        int o = (t >= d) ? ss[t - d] : 0;
        __syncthreads();
        ss[t] += o;
        __syncthreads();
    }
    if (t < NBLK) g_blockOff[t] = ss[t] - v;  // exclusive
}

__global__ void scan3_kernel() {
    int i = blockIdx.x * SCAN_BLK + threadIdx.x;
    int c = (i < NODES) ? g_cnt_in[i] : 0;
    int lane = threadIdx.x & 31, wid = threadIdx.x >> 5;
    int v = c;
#pragma unroll
    for (int d = 1; d < 32; d <<= 1) {
        int n = __shfl_up_sync(0xffffffffu, v, d);
        if (lane >= d) v += n;
    }
    __shared__ int wsum[SCAN_BLK / 32];
    if (lane == 31) wsum[wid] = v;
    __syncthreads();
    if (threadIdx.x < SCAN_BLK / 32) {
        int s = wsum[threadIdx.x];
#pragma unroll
        for (int d = 1; d < SCAN_BLK / 32; d <<= 1) {
            int n = __shfl_up_sync(0xffu, s, d);
            if ((int)threadIdx.x >= d) s += n;
        }
        wsum[threadIdx.x] = s;
    }
    __syncthreads();
    int excl = v - c + (wid > 0 ? wsum[wid - 1] : 0) + g_blockOff[blockIdx.x];
    if (i < NODES) {
        g_rowptr[i] = excl;
        g_cursor[i] = excl;
        g_ns[i] = rsqrtf(fmaxf((float)g_cnt_out[i], 1.0f));
        g_nd[i] = rsqrtf(fmaxf((float)c, 1.0f));
    }
    if (blockIdx.x == 0 && threadIdx.x == 0) g_rowptr[NODES] = EDGES;
}

// ---------------- CSR fill (by dst) -------------------------------------------
__global__ void csr_fill_kernel(const int* __restrict__ src, const int* __restrict__ dst,
                                const float* __restrict__ ew) {
    int e = blockIdx.x * blockDim.x + threadIdx.x;
    if (e < EDGES) {
        int d = dst[e];
        int p = atomicAdd(&g_cursor[d], 1);
        g_csr_src[p] = src[e];
        g_csr_w[p] = ew[e];
    }
}

// ---------------- tf32 tensor-core GEMM: t = f(A) @ W -------------------------
// MODE 0: f(A)[r,k] = A[r,k] * ns[r]
// MODE 1: f(A)[r,k] = relu(A[r,k]*nd[r] + bprev[k]) * ns[r]
// block = 128 threads (4 warps), tile 64 rows x 64 cols, K chunked by 64.
// warp = 32x32 via mma.sync.m16n8k8 tf32 (2 m-tiles x 4 n-tiles).

__device__ __forceinline__ unsigned f2tf(float f) {
    unsigned u;
    asm("cvt.rna.tf32.f32 %0, %1;" : "=r"(u) : "f"(f));
    return u;
}

__device__ __forceinline__ void mma_tf32(float* d, const unsigned* a, const unsigned* b) {
    asm volatile(
        "mma.sync.aligned.m16n8k8.row.col.f32.tf32.tf32.f32 "
        "{%0,%1,%2,%3}, {%4,%5,%6,%7}, {%8,%9}, {%0,%1,%2,%3};\n"
        : "+f"(d[0]), "+f"(d[1]), "+f"(d[2]), "+f"(d[3])
        : "r"(a[0]), "r"(a[1]), "r"(a[2]), "r"(a[3]), "r"(b[0]), "r"(b[1]));
}

#define APAD 68  // 68 % 32 = 4 -> fragment loads hit all 32 banks (conflict-free)

template <int K, int MODE>
__global__ void gemm_tc_kernel(const float* __restrict__ A, const float* __restrict__ W,
                               const float* __restrict__ bprev, float* __restrict__ out) {
    __shared__ unsigned sA[64 * APAD];  // [row][k] tf32 bits
    __shared__ unsigned sB[64 * APAD];  // [n][k]   tf32 bits (W transposed)

    const int tid = threadIdx.x;            // 0..127
    const int wid = tid >> 5;               // 0..3
    const int lane = tid & 31;
    const int qr = lane >> 2;               // 0..7
    const int qc = lane & 3;                // 0..3
    const int warp_m = wid & 1;             // 2 warps along m (32 rows each)
    const int warp_n = wid >> 1;            // 2 warps along n (32 cols each)
    const int row0 = blockIdx.x * 64;

    float acc[2][4][4];
#pragma unroll
    for (int mi = 0; mi < 2; mi++)
#pragma unroll
        for (int ni = 0; ni < 4; ni++)
#pragma unroll
            for (int j = 0; j < 4; j++) acc[mi][ni][j] = 0.0f;

    for (int chunk = 0; chunk < K; chunk += 64) {
        // ---- fill sA: 64 rows x 64 cols, transformed + cvt to tf32 ----
#pragma unroll
        for (int it = 0; it < 8; it++) {
            int idx4 = it * 128 + tid;      // 1024 float4s
            int row = idx4 >> 4;            // 0..63
            int c4 = idx4 & 15;             // 0..15 (float4 index)
            int grow = row0 + row;
            unsigned* dst = &sA[row * APAD + c4 * 4];
            if (grow < NODES) {
                float4 v = *(const float4*)&A[(long)grow * K + chunk + c4 * 4];
                float ns = g_ns[grow];
                if (MODE == 1) {
                    float nd = g_nd[grow];
                    const float4 bb = *(const float4*)&bprev[chunk + c4 * 4];
                    v.x = fmaxf(fmaf(v.x, nd, bb.x), 0.0f);
                    v.y = fmaxf(fmaf(v.y, nd, bb.y), 0.0f);
                    v.z = fmaxf(fmaf(v.z, nd, bb.z), 0.0f);
                    v.w = fmaxf(fmaf(v.w, nd, bb.w), 0.0f);
                }
                dst[0] = f2tf(v.x * ns);
                dst[1] = f2tf(v.y * ns);
                dst[2] = f2tf(v.z * ns);
                dst[3] = f2tf(v.w * ns);
            } else {
                dst[0] = 0u; dst[1] = 0u; dst[2] = 0u; dst[3] = 0u;
            }
        }
        // ---- fill sB: transpose W chunk -> sB[n][k] ----
#pragma unroll
        for (int it = 0; it < 32; it++) {
            int idx = it * 128 + tid;       // 4096 elements
            int k = idx >> 6;               // 0..63
            int n = idx & 63;               // 0..63
            sB[n * APAD + k] = f2tf(W[(long)(chunk + k) * HF + n]);
        }
        __syncthreads();

        // ---- MMA over this K chunk ----
#pragma unroll
        for (int kk8 = 0; kk8 < 8; kk8++) {
            const int kk = kk8 * 8;
            unsigned a[2][4], b[4][2];
#pragma unroll
            for (int mi = 0; mi < 2; mi++) {
                int r = warp_m * 32 + mi * 16 + qr;
                a[mi][0] = sA[r * APAD + kk + qc];
                a[mi][1] = sA[(r + 8) * APAD + kk + qc];
                a[mi][2] = sA[r * APAD + kk + qc + 4];
                a[mi][3] = sA[(r + 8) * APAD + kk + qc + 4];
            }
#pragma unroll
            for (int ni = 0; ni < 4; ni++) {
                int n = warp_n * 32 + ni * 8 + qr;
                b[ni][0] = sB[n * APAD + kk + qc];
                b[ni][1] = sB[n * APAD + kk + qc + 4];
            }
#pragma unroll
            for (int mi = 0; mi < 2; mi++)
#pragma unroll
                for (int ni = 0; ni < 4; ni++)
                    mma_tf32(acc[mi][ni], a[mi], b[ni]);
        }
        __syncthreads();
    }

    // ---- epilogue: write accumulators ----
#pragma unroll
    for (int mi = 0; mi < 2; mi++) {
        int r0 = row0 + warp_m * 32 + mi * 16 + qr;
        int r1 = r0 + 8;
#pragma unroll
        for (int ni = 0; ni < 4; ni++) {
            int col = warp_n * 32 + ni * 8 + qc * 2;
            if (r0 < NODES)
                *(float2*)&out[(long)r0 * HF + col] = make_float2(acc[mi][ni][0], acc[mi][ni][1]);
            if (r1 < NODES)
                *(float2*)&out[(long)r1 * HF + col] = make_float2(acc[mi][ni][2], acc[mi][ni][3]);
        }
    }
}

// ---------------- CSR gather aggregation: agg[d] = sum_e w_e * t[src_e] -------
__global__ void agg_kernel(const float* __restrict__ t, float* __restrict__ agg) {
    int node = blockIdx.x * 8 + (threadIdx.x >> 5);
    if (node >= NODES) return;
    int lane = threadIdx.x & 31;
    int beg = g_rowptr[node];
    int end = g_rowptr[node + 1];
    float a0 = 0.0f, a1 = 0.0f;
    int j = beg;
    for (; j + 1 < end; j += 2) {
        int s0 = g_csr_src[j];
        int s1 = g_csr_src[j + 1];
        float w0 = g_csr_w[j];
        float w1 = g_csr_w[j + 1];
        float v00 = t[(long)s0 * HF + lane];
        float v01 = t[(long)s0 * HF + 32 + lane];
        float v10 = t[(long)s1 * HF + lane];
        float v11 = t[(long)s1 * HF + 32 + lane];
        a0 = fmaf(v00, w0, a0);
        a1 = fmaf(v01, w0, a1);
        a0 = fmaf(v10, w1, a0);
        a1 = fmaf(v11, w1, a1);
    }
    if (j < end) {
        int s0 = g_csr_src[j];
        float w0 = g_csr_w[j];
        a0 = fmaf(t[(long)s0 * HF + lane], w0, a0);
        a1 = fmaf(t[(long)s0 * HF + 32 + lane], w0, a1);
    }
    agg[(long)node * HF + lane] = a0;
    agg[(long)node * HF + 32 + lane] = a1;
}

// ---------------- pool (mean per graph) + MLP head + sigmoid ------------------
__device__ __forceinline__ int lower_bound_dev(const int* __restrict__ a, int n, int key) {
    int lo = 0, hi = n;
    while (lo < hi) {
        int mid = (lo + hi) >> 1;
        if (a[mid] < key) lo = mid + 1; else hi = mid;
    }
    return lo;
}

__global__ void pool_mlp_kernel(const float* __restrict__ agg, const float* __restrict__ b3,
                                const int* __restrict__ gid,
                                const float* __restrict__ Dw1, const float* __restrict__ Db1,
                                const float* __restrict__ Dw2, const float* __restrict__ Db2,
                                const float* __restrict__ Dw3, const float* __restrict__ Db3,
                                float* __restrict__ out) {
    int g = blockIdx.x;
    int t = threadIdx.x;  // 64 threads
    int start = lower_bound_dev(gid, NODES, g);
    int end = lower_bound_dev(gid, NODES, g + 1);

    float b = b3[t];
    float sum = 0.0f;
    for (int n = start; n < end; n++) {
        float v = fmaf(agg[(long)n * HF + t], g_nd[n], b);
        sum += fmaxf(v, 0.0f);
    }
    float cnt = fmaxf((float)(end - start), 1.0f);

    __shared__ float pooled[64];
    __shared__ float h1[16];
    __shared__ float h2[8];
    pooled[t] = sum / cnt;
    __syncthreads();

    if (t < 16) {
        float s = Db1[t];
#pragma unroll
        for (int k = 0; k < 64; k++) s = fmaf(pooled[k], Dw1[k * 16 + t], s);
        h1[t] = fmaxf(s, 0.0f);
    }
    __syncthreads();
    if (t < 8) {
        float s = Db2[t];
#pragma unroll
        for (int k = 0; k < 16; k++) s = fmaf(h1[k], Dw2[k * 8 + t], s);
        h2[t] = fmaxf(s, 0.0f);
    }
    __syncthreads();
    if (t == 0) {
        float s = Db3[0];
#pragma unroll
        for (int k = 0; k < 8; k++) s = fmaf(h2[k], Dw3[k], s);
        out[g] = 1.0f / (1.0f + expf(-s));
    }
}

// ---------------- launch ------------------------------------------------------
extern "C" void kernel_launch(void* const* d_in, const int* in_sizes, int n_in,
                              void* d_out, int out_size) {
    const float* x   = (const float*)d_in[0];
    const int*   src = (const int*)d_in[1];
    const int*   dst = (const int*)d_in[2];
    const float* ew  = (const float*)d_in[3];
    const int*   gid = (const int*)d_in[4];
    const float* W1  = (const float*)d_in[5];
    const float* b1  = (const float*)d_in[6];
    const float* W2  = (const float*)d_in[7];
    const float* b2  = (const float*)d_in[8];
    const float* W3  = (const float*)d_in[9];
    const float* b3  = (const float*)d_in[10];
    const float* Dw1 = (const float*)d_in[11];
    const float* Db1 = (const float*)d_in[12];
    const float* Dw2 = (const float*)d_in[13];
    const float* Db2 = (const float*)d_in[14];
    const float* Dw3 = (const float*)d_in[15];
    const float* Db3 = (const float*)d_in[16];
    float* out = (float*)d_out;

    float* t_ptr;   cudaGetSymbolAddress((void**)&t_ptr, g_t);
    float* agg_ptr; cudaGetSymbolAddress((void**)&agg_ptr, g_agg);

    const int NB = (NODES + 255) / 256;
    const int EB = (EDGES + 255) / 256;
    const int GB = (NODES + 63) / 64;   // gemm blocks (64-row tiles)
    const int AB = (NODES + 7) / 8;     // agg blocks (8 warps each)

    // graph preprocessing
    zero_counts_kernel<<<NB, 256>>>();
    degree_kernel<<<EB, 256>>>(src, dst);
    scan1_kernel<<<NBLK, SCAN_BLK>>>();
    scan2_kernel<<<1, 512>>>();
    scan3_kernel<<<NBLK, SCAN_BLK>>>();
    csr_fill_kernel<<<EB, 256>>>(src, dst, ew);

    // layer 1: t = (x*ns)@W1 ; agg = gather(t)
    gemm_tc_kernel<INF, 0><<<GB, 128>>>(x, W1, nullptr, t_ptr);
    agg_kernel<<<AB, 256>>>(t_ptr, agg_ptr);

    // layer 2
    gemm_tc_kernel<HF, 1><<<GB, 128>>>(agg_ptr, W2, b1, t_ptr);
    agg_kernel<<<AB, 256>>>(t_ptr, agg_ptr);

    // layer 3
    gemm_tc_kernel<HF, 1><<<GB, 128>>>(agg_ptr, W3, b2, t_ptr);
    agg_kernel<<<AB, 256>>>(t_ptr, agg_ptr);

    // pool + MLP + sigmoid
    pool_mlp_kernel<<<GRAPHS, 64>>>(agg_ptr, b3, gid, Dw1, Db1, Dw2, Db2, Dw3, Db3, out);
}

// round 6
// speedup vs baseline: 1.9497x; 1.3815x over previous
#include <cuda_runtime.h>
#include <cuda_bf16.h>
#include <math.h>

// Problem constants (fixed by the dataset)
#define NODES 100000
#define EDGES 1600000
#define GRAPHS 256
#define INF 128
#define HF 64
#define SCAN_BLK 256
#define NBLK ((NODES + SCAN_BLK - 1) / SCAN_BLK)   // 391

// ---------------- scratch (static device globals; no allocation) -------------
__device__ int   g_cnt_out[NODES];
__device__ int   g_cnt_in[NODES];
__device__ float g_ns[NODES];
__device__ float g_nd[NODES];
__device__ int   g_rowptr[NODES + 1];
__device__ int   g_cursor[NODES];
__device__ int   g_csr_src[EDGES];
__device__ float g_csr_w[EDGES];
__device__ int   g_blockSums[NBLK];
__device__ int   g_blockOff[NBLK];
__device__ __nv_bfloat162 g_tb[NODES * (HF / 2)];  // GEMM output, bf16x2 packed
__device__ float g_agg[NODES * HF];                // aggregation result (fp32)

// ---------------- init: zero degree counters ---------------------------------
__global__ void zero_counts_kernel() {
    int i = blockIdx.x * blockDim.x + threadIdx.x;
    if (i < NODES) { g_cnt_out[i] = 0; g_cnt_in[i] = 0; }
}

// ---------------- degree histogram -------------------------------------------
__global__ void degree_kernel(const int* __restrict__ src, const int* __restrict__ dst) {
    int e = blockIdx.x * blockDim.x + threadIdx.x;
    if (e < EDGES) {
        atomicAdd(&g_cnt_out[src[e]], 1);
        atomicAdd(&g_cnt_in[dst[e]], 1);
    }
}

// ---------------- 3-phase parallel scan of deg_in -----------------------------
__global__ void scan1_kernel() {
    int i = blockIdx.x * SCAN_BLK + threadIdx.x;
    int c = (i < NODES) ? g_cnt_in[i] : 0;
#pragma unroll
    for (int d = 16; d; d >>= 1) c += __shfl_down_sync(0xffffffffu, c, d);
    __shared__ int w[SCAN_BLK / 32];
    if ((threadIdx.x & 31) == 0) w[threadIdx.x >> 5] = c;
    __syncthreads();
    if (threadIdx.x < SCAN_BLK / 32) {
        int s = w[threadIdx.x];
#pragma unroll
        for (int d = SCAN_BLK / 64; d; d >>= 1) s += __shfl_down_sync(0xffu, s, d);
        if (threadIdx.x == 0) g_blockSums[blockIdx.x] = s;
    }
}

__global__ void scan2_kernel() {
    __shared__ int ss[512];
    int t = threadIdx.x;
    int v = (t < NBLK) ? g_blockSums[t] : 0;
    ss[t] = v;
    __syncthreads();
    for (int d = 1; d < 512; d <<= 1) {
        int o = (t >= d) ? ss[t - d] : 0;
        __syncthreads();
        ss[t] += o;
        __syncthreads();
    }
    if (t < NBLK) g_blockOff[t] = ss[t] - v;  // exclusive
}

__global__ void scan3_kernel() {
    int i = blockIdx.x * SCAN_BLK + threadIdx.x;
    int c = (i < NODES) ? g_cnt_in[i] : 0;
    int lane = threadIdx.x & 31, wid = threadIdx.x >> 5;
    int v = c;
#pragma unroll
    for (int d = 1; d < 32; d <<= 1) {
        int n = __shfl_up_sync(0xffffffffu, v, d);
        if (lane >= d) v += n;
    }
    __shared__ int wsum[SCAN_BLK / 32];
    if (lane == 31) wsum[wid] = v;
    __syncthreads();
    if (threadIdx.x < SCAN_BLK / 32) {
        int s = wsum[threadIdx.x];
#pragma unroll
        for (int d = 1; d < SCAN_BLK / 32; d <<= 1) {
            int n = __shfl_up_sync(0xffu, s, d);
            if ((int)threadIdx.x >= d) s += n;
        }
        wsum[threadIdx.x] = s;
    }
    __syncthreads();
    int excl = v - c + (wid > 0 ? wsum[wid - 1] : 0) + g_blockOff[blockIdx.x];
    if (i < NODES) {
        g_rowptr[i] = excl;
        g_cursor[i] = excl;
        g_ns[i] = rsqrtf(fmaxf((float)g_cnt_out[i], 1.0f));
        g_nd[i] = rsqrtf(fmaxf((float)c, 1.0f));
    }
    if (blockIdx.x == 0 && threadIdx.x == 0) g_rowptr[NODES] = EDGES;
}

// ---------------- CSR fill (by dst) -------------------------------------------
__global__ void csr_fill_kernel(const int* __restrict__ src, const int* __restrict__ dst,
                                const float* __restrict__ ew) {
    int e = blockIdx.x * blockDim.x + threadIdx.x;
    if (e < EDGES) {
        int d = dst[e];
        int p = atomicAdd(&g_cursor[d], 1);
        g_csr_src[p] = src[e];
        g_csr_w[p] = ew[e];
    }
}

// ---------------- tf32 tensor-core GEMM: tb = bf16( f(A) @ W ) ----------------
// MODE 0: f(A)[r,k] = A[r,k] * ns[r]
// MODE 1: f(A)[r,k] = relu(A[r,k]*nd[r] + bprev[k]) * ns[r]
// block = 128 threads (4 warps), tile 64 rows x 64 cols, K chunked by 64.
// warp = 32x32 via mma.sync.m16n8k8 tf32 (2 m-tiles x 4 n-tiles).

__device__ __forceinline__ unsigned f2tf(float f) {
    unsigned u;
    asm("cvt.rna.tf32.f32 %0, %1;" : "=r"(u) : "f"(f));
    return u;
}

__device__ __forceinline__ void mma_tf32(float* d, const unsigned* a, const unsigned* b) {
    asm volatile(
        "mma.sync.aligned.m16n8k8.row.col.f32.tf32.tf32.f32 "
        "{%0,%1,%2,%3}, {%4,%5,%6,%7}, {%8,%9}, {%0,%1,%2,%3};\n"
        : "+f"(d[0]), "+f"(d[1]), "+f"(d[2]), "+f"(d[3])
        : "r"(a[0]), "r"(a[1]), "r"(a[2]), "r"(a[3]), "r"(b[0]), "r"(b[1]));
}

#define APAD 68  // 68 % 32 = 4 -> fragment loads hit all 32 banks (conflict-free)

template <int K, int MODE>
__global__ void gemm_tc_kernel(const float* __restrict__ A, const float* __restrict__ W,
                               const float* __restrict__ bprev,
                               __nv_bfloat162* __restrict__ outb) {
    __shared__ unsigned sA[64 * APAD];  // [row][k] tf32 bits
    __shared__ unsigned sB[64 * APAD];  // [n][k]   tf32 bits (W transposed)

    const int tid = threadIdx.x;            // 0..127
    const int wid = tid >> 5;               // 0..3
    const int lane = tid & 31;
    const int qr = lane >> 2;               // 0..7
    const int qc = lane & 3;                // 0..3
    const int warp_m = wid & 1;             // 2 warps along m (32 rows each)
    const int warp_n = wid >> 1;            // 2 warps along n (32 cols each)
    const int row0 = blockIdx.x * 64;

    float acc[2][4][4];
#pragma unroll
    for (int mi = 0; mi < 2; mi++)
#pragma unroll
        for (int ni = 0; ni < 4; ni++)
#pragma unroll
            for (int j = 0; j < 4; j++) acc[mi][ni][j] = 0.0f;

    for (int chunk = 0; chunk < K; chunk += 64) {
        // ---- fill sA: 64 rows x 64 cols, transformed + cvt to tf32 ----
#pragma unroll
        for (int it = 0; it < 8; it++) {
            int idx4 = it * 128 + tid;      // 1024 float4s
            int row = idx4 >> 4;            // 0..63
            int c4 = idx4 & 15;             // 0..15 (float4 index)
            int grow = row0 + row;
            unsigned* dst = &sA[row * APAD + c4 * 4];
            if (grow < NODES) {
                float4 v = *(const float4*)&A[(long)grow * K + chunk + c4 * 4];
                float ns = g_ns[grow];
                if (MODE == 1) {
                    float nd = g_nd[grow];
                    const float4 bb = *(const float4*)&bprev[chunk + c4 * 4];
                    v.x = fmaxf(fmaf(v.x, nd, bb.x), 0.0f);
                    v.y = fmaxf(fmaf(v.y, nd, bb.y), 0.0f);
                    v.z = fmaxf(fmaf(v.z, nd, bb.z), 0.0f);
                    v.w = fmaxf(fmaf(v.w, nd, bb.w), 0.0f);
                }
                dst[0] = f2tf(v.x * ns);
                dst[1] = f2tf(v.y * ns);
                dst[2] = f2tf(v.z * ns);
                dst[3] = f2tf(v.w * ns);
            } else {
                dst[0] = 0u; dst[1] = 0u; dst[2] = 0u; dst[3] = 0u;
            }
        }
        // ---- fill sB: transpose W chunk -> sB[n][k] ----
#pragma unroll
        for (int it = 0; it < 32; it++) {
            int idx = it * 128 + tid;       // 4096 elements
            int k = idx >> 6;               // 0..63
            int n = idx & 63;               // 0..63
            sB[n * APAD + k] = f2tf(W[(long)(chunk + k) * HF + n]);
        }
        __syncthreads();

        // ---- MMA over this K chunk ----
#pragma unroll
        for (int kk8 = 0; kk8 < 8; kk8++) {
            const int kk = kk8 * 8;
            unsigned a[2][4], b[4][2];
#pragma unroll
            for (int mi = 0; mi < 2; mi++) {
                int r = warp_m * 32 + mi * 16 + qr;
                a[mi][0] = sA[r * APAD + kk + qc];
                a[mi][1] = sA[(r + 8) * APAD + kk + qc];
                a[mi][2] = sA[r * APAD + kk + qc + 4];
                a[mi][3] = sA[(r + 8) * APAD + kk + qc + 4];
            }
#pragma unroll
            for (int ni = 0; ni < 4; ni++) {
                int n = warp_n * 32 + ni * 8 + qr;
                b[ni][0] = sB[n * APAD + kk + qc];
                b[ni][1] = sB[n * APAD + kk + qc + 4];
            }
#pragma unroll
            for (int mi = 0; mi < 2; mi++)
#pragma unroll
                for (int ni = 0; ni < 4; ni++)
                    mma_tf32(acc[mi][ni], a[mi], b[ni]);
        }
        __syncthreads();
    }

    // ---- epilogue: pack accumulator pairs to bf16x2 (cols come in even pairs) ----
#pragma unroll
    for (int mi = 0; mi < 2; mi++) {
        int r0 = row0 + warp_m * 32 + mi * 16 + qr;
        int r1 = r0 + 8;
#pragma unroll
        for (int ni = 0; ni < 4; ni++) {
            int col2 = (warp_n * 32 + ni * 8 + qc * 2) >> 1;  // bf16x2 index
            if (r0 < NODES)
                outb[(long)r0 * (HF / 2) + col2] =
                    __floats2bfloat162_rn(acc[mi][ni][0], acc[mi][ni][1]);
            if (r1 < NODES)
                outb[(long)r1 * (HF / 2) + col2] =
                    __floats2bfloat162_rn(acc[mi][ni][2], acc[mi][ni][3]);
        }
    }
}

// ---------------- CSR gather aggregation (bf16 source): 1 line per edge -------
// warp per dst node; lane handles features {2*lane, 2*lane+1} via one bf16x2.
__global__ void agg_kernel(const __nv_bfloat162* __restrict__ tb, float* __restrict__ agg) {
    int node = blockIdx.x * 8 + (threadIdx.x >> 5);
    if (node >= NODES) return;
    int lane = threadIdx.x & 31;
    int beg = g_rowptr[node];
    int end = g_rowptr[node + 1];
    float a0 = 0.0f, a1 = 0.0f;
    int j = beg;
    for (; j + 3 < end; j += 4) {
        int s0 = g_csr_src[j];
        int s1 = g_csr_src[j + 1];
        int s2 = g_csr_src[j + 2];
        int s3 = g_csr_src[j + 3];
        float w0 = g_csr_w[j];
        float w1 = g_csr_w[j + 1];
        float w2 = g_csr_w[j + 2];
        float w3 = g_csr_w[j + 3];
        float2 f0 = __bfloat1622float2(tb[(long)s0 * (HF / 2) + lane]);
        float2 f1 = __bfloat1622float2(tb[(long)s1 * (HF / 2) + lane]);
        float2 f2 = __bfloat1622float2(tb[(long)s2 * (HF / 2) + lane]);
        float2 f3 = __bfloat1622float2(tb[(long)s3 * (HF / 2) + lane]);
        a0 = fmaf(f0.x, w0, a0); a1 = fmaf(f0.y, w0, a1);
        a0 = fmaf(f1.x, w1, a0); a1 = fmaf(f1.y, w1, a1);
        a0 = fmaf(f2.x, w2, a0); a1 = fmaf(f2.y, w2, a1);
        a0 = fmaf(f3.x, w3, a0); a1 = fmaf(f3.y, w3, a1);
    }
    for (; j < end; j++) {
        int s0 = g_csr_src[j];
        float w0 = g_csr_w[j];
        float2 f0 = __bfloat1622float2(tb[(long)s0 * (HF / 2) + lane]);
        a0 = fmaf(f0.x, w0, a0);
        a1 = fmaf(f0.y, w0, a1);
    }
    *(float2*)&agg[(long)node * HF + 2 * lane] = make_float2(a0, a1);
}

// ---------------- pool (mean per graph) + MLP head + sigmoid ------------------
__device__ __forceinline__ int lower_bound_dev(const int* __restrict__ a, int n, int key) {
    int lo = 0, hi = n;
    while (lo < hi) {
        int mid = (lo + hi) >> 1;
        if (a[mid] < key) lo = mid + 1; else hi = mid;
    }
    return lo;
}

__global__ void pool_mlp_kernel(const float* __restrict__ agg, const float* __restrict__ b3,
                                const int* __restrict__ gid,
                                const float* __restrict__ Dw1, const float* __restrict__ Db1,
                                const float* __restrict__ Dw2, const float* __restrict__ Db2,
                                const float* __restrict__ Dw3, const float* __restrict__ Db3,
                                float* __restrict__ out) {
    int g = blockIdx.x;
    int t = threadIdx.x;  // 64 threads
    int start = lower_bound_dev(gid, NODES, g);
    int end = lower_bound_dev(gid, NODES, g + 1);

    float b = b3[t];
    float sum = 0.0f;
    for (int n = start; n < end; n++) {
        float v = fmaf(agg[(long)n * HF + t], g_nd[n], b);
        sum += fmaxf(v, 0.0f);
    }
    float cnt = fmaxf((float)(end - start), 1.0f);

    __shared__ float pooled[64];
    __shared__ float h1[16];
    __shared__ float h2[8];
    pooled[t] = sum / cnt;
    __syncthreads();

    if (t < 16) {
        float s = Db1[t];
#pragma unroll
        for (int k = 0; k < 64; k++) s = fmaf(pooled[k], Dw1[k * 16 + t], s);
        h1[t] = fmaxf(s, 0.0f);
    }
    __syncthreads();
    if (t < 8) {
        float s = Db2[t];
#pragma unroll
        for (int k = 0; k < 16; k++) s = fmaf(h1[k], Dw2[k * 8 + t], s);
        h2[t] = fmaxf(s, 0.0f);
    }
    __syncthreads();
    if (t == 0) {
        float s = Db3[0];
#pragma unroll
        for (int k = 0; k < 8; k++) s = fmaf(h2[k], Dw3[k], s);
        out[g] = 1.0f / (1.0f + expf(-s));
    }
}

// ---------------- launch ------------------------------------------------------
extern "C" void kernel_launch(void* const* d_in, const int* in_sizes, int n_in,
                              void* d_out, int out_size) {
    const float* x   = (const float*)d_in[0];
    const int*   src = (const int*)d_in[1];
    const int*   dst = (const int*)d_in[2];
    const float* ew  = (const float*)d_in[3];
    const int*   gid = (const int*)d_in[4];
    const float* W1  = (const float*)d_in[5];
    const float* b1  = (const float*)d_in[6];
    const float* W2  = (const float*)d_in[7];
    const float* b2  = (const float*)d_in[8];
    const float* W3  = (const float*)d_in[9];
    const float* b3  = (const float*)d_in[10];
    const float* Dw1 = (const float*)d_in[11];
    const float* Db1 = (const float*)d_in[12];
    const float* Dw2 = (const float*)d_in[13];
    const float* Db2 = (const float*)d_in[14];
    const float* Dw3 = (const float*)d_in[15];
    const float* Db3 = (const float*)d_in[16];
    float* out = (float*)d_out;

    __nv_bfloat162* tb_ptr; cudaGetSymbolAddress((void**)&tb_ptr, g_tb);
    float* agg_ptr;         cudaGetSymbolAddress((void**)&agg_ptr, g_agg);

    const int NB = (NODES + 255) / 256;
    const int EB = (EDGES + 255) / 256;
    const int GB = (NODES + 63) / 64;   // gemm blocks (64-row tiles)
    const int AB = (NODES + 7) / 8;     // agg blocks (8 warps each)

    // graph preprocessing
    zero_counts_kernel<<<NB, 256>>>();
    degree_kernel<<<EB, 256>>>(src, dst);
    scan1_kernel<<<NBLK, SCAN_BLK>>>();
    scan2_kernel<<<1, 512>>>();
    scan3_kernel<<<NBLK, SCAN_BLK>>>();
    csr_fill_kernel<<<EB, 256>>>(src, dst, ew);

    // layer 1: tb = bf16((x*ns)@W1) ; agg = gather(tb)
    gemm_tc_kernel<INF, 0><<<GB, 128>>>(x, W1, nullptr, tb_ptr);
    agg_kernel<<<AB, 256>>>(tb_ptr, agg_ptr);

    // layer 2
    gemm_tc_kernel<HF, 1><<<GB, 128>>>(agg_ptr, W2, b1, tb_ptr);
    agg_kernel<<<AB, 256>>>(tb_ptr, agg_ptr);

    // layer 3
    gemm_tc_kernel<HF, 1><<<GB, 128>>>(agg_ptr, W3, b2, tb_ptr);
    agg_kernel<<<AB, 256>>>(tb_ptr, agg_ptr);

    // pool + MLP + sigmoid
    pool_mlp_kernel<<<GRAPHS, 64>>>(agg_ptr, b3, gid, Dw1, Db1, Dw2, Db2, Dw3, Db3, out);
}

// round 7
// speedup vs baseline: 2.0159x; 1.0339x over previous
#include <cuda_runtime.h>
#include <cuda_bf16.h>
#include <math.h>

// Problem constants (fixed by the dataset)
#define NODES 100000
#define EDGES 1600000
#define GRAPHS 256
#define INF 128
#define HF 64
#define SCAN_BLK 256
#define NBLK ((NODES + SCAN_BLK - 1) / SCAN_BLK)   // 391

// ---------------- scratch (static device globals; no allocation) -------------
__device__ int   g_cnt_out[NODES];
__device__ int   g_cnt_in[NODES];
__device__ float g_ns[NODES];
__device__ float g_nd[NODES];
__device__ int   g_rowptr[NODES + 1];
__device__ int   g_cursor[NODES];
__device__ int2  g_csr[EDGES];                     // {src, w-bits}
__device__ int   g_blockSums[NBLK];
__device__ int   g_blockOff[NBLK];
__device__ __nv_bfloat162 g_tb[NODES * (HF / 2)];  // per-layer GEMM output (bf16x2)
__device__ float g_aggf[NODES * HF];               // layer-3 activated output (fp32)

// ---------------- init: zero degree counters ---------------------------------
__global__ void zero_counts_kernel() {
    int i = blockIdx.x * blockDim.x + threadIdx.x;
    if (i < NODES) { g_cnt_out[i] = 0; g_cnt_in[i] = 0; }
}

// ---------------- degree histogram -------------------------------------------
__global__ void degree_kernel(const int* __restrict__ src, const int* __restrict__ dst) {
    int e = blockIdx.x * blockDim.x + threadIdx.x;
    if (e < EDGES) {
        atomicAdd(&g_cnt_out[src[e]], 1);
        atomicAdd(&g_cnt_in[dst[e]], 1);
    }
}

// ---------------- norms (needs only degree counts) ----------------------------
__global__ void norm_kernel() {
    int i = blockIdx.x * blockDim.x + threadIdx.x;
    if (i < NODES) {
        g_ns[i] = rsqrtf(fmaxf((float)g_cnt_out[i], 1.0f));
        g_nd[i] = rsqrtf(fmaxf((float)g_cnt_in[i], 1.0f));
    }
}

// ---------------- 3-phase parallel scan of deg_in -----------------------------
__global__ void scan1_kernel() {
    int i = blockIdx.x * SCAN_BLK + threadIdx.x;
    int c = (i < NODES) ? g_cnt_in[i] : 0;
#pragma unroll
    for (int d = 16; d; d >>= 1) c += __shfl_down_sync(0xffffffffu, c, d);
    __shared__ int w[SCAN_BLK / 32];
    if ((threadIdx.x & 31) == 0) w[threadIdx.x >> 5] = c;
    __syncthreads();
    if (threadIdx.x < SCAN_BLK / 32) {
        int s = w[threadIdx.x];
#pragma unroll
        for (int d = SCAN_BLK / 64; d; d >>= 1) s += __shfl_down_sync(0xffu, s, d);
        if (threadIdx.x == 0) g_blockSums[blockIdx.x] = s;
    }
}

__global__ void scan2_kernel() {
    __shared__ int ss[512];
    int t = threadIdx.x;
    int v = (t < NBLK) ? g_blockSums[t] : 0;
    ss[t] = v;
    __syncthreads();
    for (int d = 1; d < 512; d <<= 1) {
        int o = (t >= d) ? ss[t - d] : 0;
        __syncthreads();
        ss[t] += o;
        __syncthreads();
    }
    if (t < NBLK) g_blockOff[t] = ss[t] - v;  // exclusive
}

__global__ void scan3_kernel() {
    int i = blockIdx.x * SCAN_BLK + threadIdx.x;
    int c = (i < NODES) ? g_cnt_in[i] : 0;
    int lane = threadIdx.x & 31, wid = threadIdx.x >> 5;
    int v = c;
#pragma unroll
    for (int d = 1; d < 32; d <<= 1) {
        int n = __shfl_up_sync(0xffffffffu, v, d);
        if (lane >= d) v += n;
    }
    __shared__ int wsum[SCAN_BLK / 32];
    if (lane == 31) wsum[wid] = v;
    __syncthreads();
    if (threadIdx.x < SCAN_BLK / 32) {
        int s = wsum[threadIdx.x];
#pragma unroll
        for (int d = 1; d < SCAN_BLK / 32; d <<= 1) {
            int n = __shfl_up_sync(0xffu, s, d);
            if ((int)threadIdx.x >= d) s += n;
        }
        wsum[threadIdx.x] = s;
    }
    __syncthreads();
    int excl = v - c + (wid > 0 ? wsum[wid - 1] : 0) + g_blockOff[blockIdx.x];
    if (i < NODES) {
        g_rowptr[i] = excl;
        g_cursor[i] = excl;
    }
    if (blockIdx.x == 0 && threadIdx.x == 0) g_rowptr[NODES] = EDGES;
}

// ---------------- CSR fill (by dst), packed int2 ------------------------------
__global__ void csr_fill_kernel(const int* __restrict__ src, const int* __restrict__ dst,
                                const float* __restrict__ ew) {
    int e = blockIdx.x * blockDim.x + threadIdx.x;
    if (e < EDGES) {
        int d = dst[e];
        int p = atomicAdd(&g_cursor[d], 1);
        g_csr[p] = make_int2(src[e], __float_as_int(ew[e]));
    }
}

// ---------------- layer-1 tf32 GEMM: tb = bf16( (x*ns) @ W1 ) -----------------
__device__ __forceinline__ unsigned f2tf(float f) {
    unsigned u;
    asm("cvt.rna.tf32.f32 %0, %1;" : "=r"(u) : "f"(f));
    return u;
}

__device__ __forceinline__ void mma_tf32(float* d, const unsigned* a, const unsigned* b) {
    asm volatile(
        "mma.sync.aligned.m16n8k8.row.col.f32.tf32.tf32.f32 "
        "{%0,%1,%2,%3}, {%4,%5,%6,%7}, {%8,%9}, {%0,%1,%2,%3};\n"
        : "+f"(d[0]), "+f"(d[1]), "+f"(d[2]), "+f"(d[3])
        : "r"(a[0]), "r"(a[1]), "r"(a[2]), "r"(a[3]), "r"(b[0]), "r"(b[1]));
}

#define APAD 68  // 68 % 32 = 4 -> fragment loads hit all 32 banks (conflict-free)

__global__ void gemm1_kernel(const float* __restrict__ A, const float* __restrict__ W,
                             __nv_bfloat162* __restrict__ outb) {
    __shared__ unsigned sA[64 * APAD];
    __shared__ unsigned sB[64 * APAD];

    const int tid = threadIdx.x;            // 0..127
    const int wid = tid >> 5;
    const int lane = tid & 31;
    const int qr = lane >> 2;
    const int qc = lane & 3;
    const int warp_m = wid & 1;
    const int warp_n = wid >> 1;
    const int row0 = blockIdx.x * 64;

    float acc[2][4][4];
#pragma unroll
    for (int mi = 0; mi < 2; mi++)
#pragma unroll
        for (int ni = 0; ni < 4; ni++)
#pragma unroll
            for (int j = 0; j < 4; j++) acc[mi][ni][j] = 0.0f;

    for (int chunk = 0; chunk < INF; chunk += 64) {
#pragma unroll
        for (int it = 0; it < 8; it++) {
            int idx4 = it * 128 + tid;
            int row = idx4 >> 4;
            int c4 = idx4 & 15;
            int grow = row0 + row;
            unsigned* dst = &sA[row * APAD + c4 * 4];
            if (grow < NODES) {
                float4 v = *(const float4*)&A[(long)grow * INF + chunk + c4 * 4];
                float ns = g_ns[grow];
                dst[0] = f2tf(v.x * ns);
                dst[1] = f2tf(v.y * ns);
                dst[2] = f2tf(v.z * ns);
                dst[3] = f2tf(v.w * ns);
            } else {
                dst[0] = 0u; dst[1] = 0u; dst[2] = 0u; dst[3] = 0u;
            }
        }
#pragma unroll
        for (int it = 0; it < 32; it++) {
            int idx = it * 128 + tid;
            int k = idx >> 6;
            int n = idx & 63;
            sB[n * APAD + k] = f2tf(W[(long)(chunk + k) * HF + n]);
        }
        __syncthreads();

#pragma unroll
        for (int kk8 = 0; kk8 < 8; kk8++) {
            const int kk = kk8 * 8;
            unsigned a[2][4], b[4][2];
#pragma unroll
            for (int mi = 0; mi < 2; mi++) {
                int r = warp_m * 32 + mi * 16 + qr;
                a[mi][0] = sA[r * APAD + kk + qc];
                a[mi][1] = sA[(r + 8) * APAD + kk + qc];
                a[mi][2] = sA[r * APAD + kk + qc + 4];
                a[mi][3] = sA[(r + 8) * APAD + kk + qc + 4];
            }
#pragma unroll
            for (int ni = 0; ni < 4; ni++) {
                int n = warp_n * 32 + ni * 8 + qr;
                b[ni][0] = sB[n * APAD + kk + qc];
                b[ni][1] = sB[n * APAD + kk + qc + 4];
            }
#pragma unroll
            for (int mi = 0; mi < 2; mi++)
#pragma unroll
                for (int ni = 0; ni < 4; ni++)
                    mma_tf32(acc[mi][ni], a[mi], b[ni]);
        }
        __syncthreads();
    }

#pragma unroll
    for (int mi = 0; mi < 2; mi++) {
        int r0 = row0 + warp_m * 32 + mi * 16 + qr;
        int r1 = r0 + 8;
#pragma unroll
        for (int ni = 0; ni < 4; ni++) {
            int col2 = (warp_n * 32 + ni * 8 + qc * 2) >> 1;
            if (r0 < NODES)
                outb[(long)r0 * (HF / 2) + col2] =
                    __floats2bfloat162_rn(acc[mi][ni][0], acc[mi][ni][1]);
            if (r1 < NODES)
                outb[(long)r1 * (HF / 2) + col2] =
                    __floats2bfloat162_rn(acc[mi][ni][2], acc[mi][ni][3]);
        }
    }
}

// ---------------- fused layer: agg(tb_in) -> transform -> bf16 GEMM -> tb_out -
// Block = 256 threads (8 warps), 64-row tile.
// Phase A: warp w aggregates nodes [row0+8w, row0+8w+8): lane handles feature
//          pair (2*lane, 2*lane+1); h = relu(sum*nd + b)*ns -> smem bf16.
// Phase B: 64x64 GEMM h @ W via mma.m16n8k16 bf16; warp = 16 rows x 32 cols.
#define BPAD 72  // bf16 elems per row; 144B stride -> conflict-free frag loads

__device__ __forceinline__ void mma_bf16(float* d, const unsigned* a, const unsigned* b) {
    asm volatile(
        "mma.sync.aligned.m16n8k16.row.col.f32.bf16.bf16.f32 "
        "{%0,%1,%2,%3}, {%4,%5,%6,%7}, {%8,%9}, {%0,%1,%2,%3};\n"
        : "+f"(d[0]), "+f"(d[1]), "+f"(d[2]), "+f"(d[3])
        : "r"(a[0]), "r"(a[1]), "r"(a[2]), "r"(a[3]), "r"(b[0]), "r"(b[1]));
}

__global__ void fused_layer_kernel(const __nv_bfloat162* __restrict__ tb_in,
                                   const float* __restrict__ W,
                                   const float* __restrict__ bprev,
                                   __nv_bfloat162* __restrict__ tb_out) {
    __shared__ __nv_bfloat16 sA[64 * BPAD];  // [row][k]
    __shared__ __nv_bfloat16 sW[64 * BPAD];  // [n][k] (W transposed)

    const int tid = threadIdx.x;     // 0..255
    const int wid = tid >> 5;        // 0..7
    const int lane = tid & 31;
    const int row0 = blockIdx.x * 64;

    // load W transposed -> sW[n][k]
#pragma unroll
    for (int it = 0; it < 16; it++) {
        int idx = it * 256 + tid;    // 4096
        int k = idx >> 6;
        int n = idx & 63;
        sW[n * BPAD + k] = __float2bfloat16(W[k * HF + n]);
    }

    // Phase A: aggregate 8 nodes per warp
    const float bx = bprev[2 * lane];
    const float by = bprev[2 * lane + 1];
#pragma unroll 1
    for (int r = 0; r < 8; r++) {
        int lrow = wid * 8 + r;
        int row = row0 + lrow;
        float a0 = 0.0f, a1 = 0.0f;
        if (row < NODES) {
            int beg = g_rowptr[row];
            int end = g_rowptr[row + 1];
            int j = beg;
            for (; j + 3 < end; j += 4) {
                int2 e0 = g_csr[j];
                int2 e1 = g_csr[j + 1];
                int2 e2 = g_csr[j + 2];
                int2 e3 = g_csr[j + 3];
                float2 f0 = __bfloat1622float2(tb_in[(long)e0.x * (HF / 2) + lane]);
                float2 f1 = __bfloat1622float2(tb_in[(long)e1.x * (HF / 2) + lane]);
                float2 f2 = __bfloat1622float2(tb_in[(long)e2.x * (HF / 2) + lane]);
                float2 f3 = __bfloat1622float2(tb_in[(long)e3.x * (HF / 2) + lane]);
                float w0 = __int_as_float(e0.y), w1 = __int_as_float(e1.y);
                float w2 = __int_as_float(e2.y), w3 = __int_as_float(e3.y);
                a0 = fmaf(f0.x, w0, a0); a1 = fmaf(f0.y, w0, a1);
                a0 = fmaf(f1.x, w1, a0); a1 = fmaf(f1.y, w1, a1);
                a0 = fmaf(f2.x, w2, a0); a1 = fmaf(f2.y, w2, a1);
                a0 = fmaf(f3.x, w3, a0); a1 = fmaf(f3.y, w3, a1);
            }
            for (; j < end; j++) {
                int2 e0 = g_csr[j];
                float2 f0 = __bfloat1622float2(tb_in[(long)e0.x * (HF / 2) + lane]);
                float w0 = __int_as_float(e0.y);
                a0 = fmaf(f0.x, w0, a0);
                a1 = fmaf(f0.y, w0, a1);
            }
            float nd = g_nd[row];
            float ns = g_ns[row];
            a0 = fmaxf(fmaf(a0, nd, bx), 0.0f) * ns;
            a1 = fmaxf(fmaf(a1, nd, by), 0.0f) * ns;
        }
        *(__nv_bfloat162*)&sA[lrow * BPAD + 2 * lane] = __floats2bfloat162_rn(a0, a1);
    }
    __syncthreads();

    // Phase B: GEMM sA @ sW^T; warp_m = wid&3 (16 rows), warp_n = wid>>2 (32 cols)
    const int warp_m = wid & 3;
    const int warp_n = wid >> 2;
    const int qr = lane >> 2;
    const int qc = lane & 3;

    float acc[4][4];
#pragma unroll
    for (int ni = 0; ni < 4; ni++)
#pragma unroll
        for (int j = 0; j < 4; j++) acc[ni][j] = 0.0f;

#pragma unroll
    for (int ks = 0; ks < 4; ks++) {
        const int kk = ks * 16;
        unsigned a[4], b[4][2];
        int ra = warp_m * 16 + qr;
        a[0] = *(const unsigned*)&sA[ra * BPAD + kk + 2 * qc];
        a[1] = *(const unsigned*)&sA[(ra + 8) * BPAD + kk + 2 * qc];
        a[2] = *(const unsigned*)&sA[ra * BPAD + kk + 2 * qc + 8];
        a[3] = *(const unsigned*)&sA[(ra + 8) * BPAD + kk + 2 * qc + 8];
#pragma unroll
        for (int ni = 0; ni < 4; ni++) {
            int n = warp_n * 32 + ni * 8 + qr;
            b[ni][0] = *(const unsigned*)&sW[n * BPAD + kk + 2 * qc];
            b[ni][1] = *(const unsigned*)&sW[n * BPAD + kk + 2 * qc + 8];
        }
#pragma unroll
        for (int ni = 0; ni < 4; ni++)
            mma_bf16(acc[ni], a, b[ni]);
    }

    // epilogue
    int r0 = row0 + warp_m * 16 + qr;
    int r1 = r0 + 8;
#pragma unroll
    for (int ni = 0; ni < 4; ni++) {
        int col2 = (warp_n * 32 + ni * 8 + qc * 2) >> 1;
        if (r0 < NODES)
            tb_out[(long)r0 * (HF / 2) + col2] = __floats2bfloat162_rn(acc[ni][0], acc[ni][1]);
        if (r1 < NODES)
            tb_out[(long)r1 * (HF / 2) + col2] = __floats2bfloat162_rn(acc[ni][2], acc[ni][3]);
    }
}

// ---------------- layer-3 agg + activate: aggf = relu(agg*nd + b3) ------------
__global__ void agg3_kernel(const __nv_bfloat162* __restrict__ tb,
                            const float* __restrict__ b3,
                            float* __restrict__ out) {
    int node = blockIdx.x * 8 + (threadIdx.x >> 5);
    if (node >= NODES) return;
    int lane = threadIdx.x & 31;
    int beg = g_rowptr[node];
    int end = g_rowptr[node + 1];
    float a0 = 0.0f, a1 = 0.0f;
    int j = beg;
    for (; j + 3 < end; j += 4) {
        int2 e0 = g_csr[j];
        int2 e1 = g_csr[j + 1];
        int2 e2 = g_csr[j + 2];
        int2 e3 = g_csr[j + 3];
        float2 f0 = __bfloat1622float2(tb[(long)e0.x * (HF / 2) + lane]);
        float2 f1 = __bfloat1622float2(tb[(long)e1.x * (HF / 2) + lane]);
        float2 f2 = __bfloat1622float2(tb[(long)e2.x * (HF / 2) + lane]);
        float2 f3 = __bfloat1622float2(tb[(long)e3.x * (HF / 2) + lane]);
        float w0 = __int_as_float(e0.y), w1 = __int_as_float(e1.y);
        float w2 = __int_as_float(e2.y), w3 = __int_as_float(e3.y);
        a0 = fmaf(f0.x, w0, a0); a1 = fmaf(f0.y, w0, a1);
        a0 = fmaf(f1.x, w1, a0); a1 = fmaf(f1.y, w1, a1);
        a0 = fmaf(f2.x, w2, a0); a1 = fmaf(f2.y, w2, a1);
        a0 = fmaf(f3.x, w3, a0); a1 = fmaf(f3.y, w3, a1);
    }
    for (; j < end; j++) {
        int2 e0 = g_csr[j];
        float2 f0 = __bfloat1622float2(tb[(long)e0.x * (HF / 2) + lane]);
        float w0 = __int_as_float(e0.y);
        a0 = fmaf(f0.x, w0, a0);
        a1 = fmaf(f0.y, w0, a1);
    }
    float nd = g_nd[node];
    float r0 = fmaxf(fmaf(a0, nd, b3[2 * lane]), 0.0f);
    float r1 = fmaxf(fmaf(a1, nd, b3[2 * lane + 1]), 0.0f);
    *(float2*)&out[(long)node * HF + 2 * lane] = make_float2(r0, r1);
}

// ---------------- pool (mean per graph) + MLP head + sigmoid ------------------
__device__ __forceinline__ int lower_bound_dev(const int* __restrict__ a, int n, int key) {
    int lo = 0, hi = n;
    while (lo < hi) {
        int mid = (lo + hi) >> 1;
        if (a[mid] < key) lo = mid + 1; else hi = mid;
    }
    return lo;
}

__global__ void pool_mlp_kernel(const float* __restrict__ aggf,
                                const int* __restrict__ gid,
                                const float* __restrict__ Dw1, const float* __restrict__ Db1,
                                const float* __restrict__ Dw2, const float* __restrict__ Db2,
                                const float* __restrict__ Dw3, const float* __restrict__ Db3,
                                float* __restrict__ out) {
    int g = blockIdx.x;
    int t = threadIdx.x;  // 64 threads
    int start = lower_bound_dev(gid, NODES, g);
    int end = lower_bound_dev(gid, NODES, g + 1);

    float sum = 0.0f;
    for (int n = start; n < end; n++) sum += aggf[(long)n * HF + t];
    float cnt = fmaxf((float)(end - start), 1.0f);

    __shared__ float pooled[64];
    __shared__ float h1[16];
    __shared__ float h2[8];
    pooled[t] = sum / cnt;
    __syncthreads();

    if (t < 16) {
        float s = Db1[t];
#pragma unroll
        for (int k = 0; k < 64; k++) s = fmaf(pooled[k], Dw1[k * 16 + t], s);
        h1[t] = fmaxf(s, 0.0f);
    }
    __syncthreads();
    if (t < 8) {
        float s = Db2[t];
#pragma unroll
        for (int k = 0; k < 16; k++) s = fmaf(h1[k], Dw2[k * 8 + t], s);
        h2[t] = fmaxf(s, 0.0f);
    }
    __syncthreads();
    if (t == 0) {
        float s = Db3[0];
#pragma unroll
        for (int k = 0; k < 8; k++) s = fmaf(h2[k], Dw3[k], s);
        out[g] = 1.0f / (1.0f + expf(-s));
    }
}

// ---------------- launch ------------------------------------------------------
extern "C" void kernel_launch(void* const* d_in, const int* in_sizes, int n_in,
                              void* d_out, int out_size) {
    const float* x   = (const float*)d_in[0];
    const int*   src = (const int*)d_in[1];
    const int*   dst = (const int*)d_in[2];
    const float* ew  = (const float*)d_in[3];
    const int*   gid = (const int*)d_in[4];
    const float* W1  = (const float*)d_in[5];
    const float* b1  = (const float*)d_in[6];
    const float* W2  = (const float*)d_in[7];
    const float* b2  = (const float*)d_in[8];
    const float* W3  = (const float*)d_in[9];
    const float* b3  = (const float*)d_in[10];
    const float* Dw1 = (const float*)d_in[11];
    const float* Db1 = (const float*)d_in[12];
    const float* Dw2 = (const float*)d_in[13];
    const float* Db2 = (const float*)d_in[14];
    const float* Dw3 = (const float*)d_in[15];
    const float* Db3 = (const float*)d_in[16];
    float* out = (float*)d_out;

    __nv_bfloat162* tb_ptr; cudaGetSymbolAddress((void**)&tb_ptr, g_tb);
    float* aggf_ptr;        cudaGetSymbolAddress((void**)&aggf_ptr, g_aggf);

    const int NB = (NODES + 255) / 256;
    const int EB = (EDGES + 255) / 256;
    const int GB = (NODES + 63) / 64;   // 64-row tiles
    const int AB = (NODES + 7) / 8;     // agg blocks (8 warps each)

    // 1-3: degree + norms (gemm1 needs only ns)
    zero_counts_kernel<<<NB, 256>>>();
    degree_kernel<<<EB, 256>>>(src, dst);
    norm_kernel<<<NB, 256>>>();

    // 4: layer-1 GEMM (profiled slot)
    gemm1_kernel<<<GB, 128>>>(x, W1, tb_ptr);

    // 5-8: CSR build
    scan1_kernel<<<NBLK, SCAN_BLK>>>();
    scan2_kernel<<<1, 512>>>();
    scan3_kernel<<<NBLK, SCAN_BLK>>>();
    csr_fill_kernel<<<EB, 256>>>(src, dst, ew);

    // 9-10: fused agg+transform+GEMM for layers 2 and 3
    fused_layer_kernel<<<GB, 256>>>(tb_ptr, W2, b1, tb_ptr);
    fused_layer_kernel<<<GB, 256>>>(tb_ptr, W3, b2, tb_ptr);

    // 11: layer-3 aggregation + activation
    agg3_kernel<<<AB, 256>>>(tb_ptr, b3, aggf_ptr);

    // 12: pool + MLP + sigmoid
    pool_mlp_kernel<<<GRAPHS, 64>>>(aggf_ptr, gid, Dw1, Db1, Dw2, Db2, Dw3, Db3, out);
}

// round 8
// speedup vs baseline: 2.1228x; 1.0531x over previous
#include <cuda_runtime.h>
#include <cuda_bf16.h>
#include <math.h>

// Problem constants (fixed by the dataset)
#define NODES 100000
#define EDGES 1600000
#define GRAPHS 256
#define INF 128
#define HF 64
#define SCAN_BLK 256
#define NBLK ((NODES + SCAN_BLK - 1) / SCAN_BLK)   // 391

// ---------------- scratch (static device globals; no allocation) -------------
__device__ int   g_cnt_out[NODES];
__device__ int   g_cnt_in[NODES];
__device__ float g_ns[NODES];
__device__ float g_nd[NODES];
__device__ int   g_rowptr[NODES + 1];
__device__ int   g_cursor[NODES];
__device__ int2  g_csr[EDGES];                     // {src, w-bits}
__device__ int   g_blockSums[NBLK];
__device__ int   g_blockOff[NBLK];
__device__ __nv_bfloat162 g_tb[NODES * (HF / 2)];  // per-layer GEMM output (bf16x2)
__device__ float g_aggf[NODES * HF];               // layer-3 activated output (fp32)

// ---------------- init: zero degree counters ---------------------------------
__global__ void zero_counts_kernel() {
    int i = blockIdx.x * blockDim.x + threadIdx.x;
    if (i < NODES) { g_cnt_out[i] = 0; g_cnt_in[i] = 0; }
}

// ---------------- degree histogram -------------------------------------------
__global__ void degree_kernel(const int* __restrict__ src, const int* __restrict__ dst) {
    int e = blockIdx.x * blockDim.x + threadIdx.x;
    if (e < EDGES) {
        atomicAdd(&g_cnt_out[src[e]], 1);
        atomicAdd(&g_cnt_in[dst[e]], 1);
    }
}

// ---------------- norms (needs only degree counts) ----------------------------
__global__ void norm_kernel() {
    int i = blockIdx.x * blockDim.x + threadIdx.x;
    if (i < NODES) {
        g_ns[i] = rsqrtf(fmaxf((float)g_cnt_out[i], 1.0f));
        g_nd[i] = rsqrtf(fmaxf((float)g_cnt_in[i], 1.0f));
    }
}

// ---------------- 3-phase parallel scan of deg_in -----------------------------
__global__ void scan1_kernel() {
    int i = blockIdx.x * SCAN_BLK + threadIdx.x;
    int c = (i < NODES) ? g_cnt_in[i] : 0;
#pragma unroll
    for (int d = 16; d; d >>= 1) c += __shfl_down_sync(0xffffffffu, c, d);
    __shared__ int w[SCAN_BLK / 32];
    if ((threadIdx.x & 31) == 0) w[threadIdx.x >> 5] = c;
    __syncthreads();
    if (threadIdx.x < SCAN_BLK / 32) {
        int s = w[threadIdx.x];
#pragma unroll
        for (int d = SCAN_BLK / 64; d; d >>= 1) s += __shfl_down_sync(0xffu, s, d);
        if (threadIdx.x == 0) g_blockSums[blockIdx.x] = s;
    }
}

__global__ void scan2_kernel() {
    __shared__ int ss[512];
    int t = threadIdx.x;
    int v = (t < NBLK) ? g_blockSums[t] : 0;
    ss[t] = v;
    __syncthreads();
    for (int d = 1; d < 512; d <<= 1) {
        int o = (t >= d) ? ss[t - d] : 0;
        __syncthreads();
        ss[t] += o;
        __syncthreads();
    }
    if (t < NBLK) g_blockOff[t] = ss[t] - v;  // exclusive
}

__global__ void scan3_kernel() {
    int i = blockIdx.x * SCAN_BLK + threadIdx.x;
    int c = (i < NODES) ? g_cnt_in[i] : 0;
    int lane = threadIdx.x & 31, wid = threadIdx.x >> 5;
    int v = c;
#pragma unroll
    for (int d = 1; d < 32; d <<= 1) {
        int n = __shfl_up_sync(0xffffffffu, v, d);
        if (lane >= d) v += n;
    }
    __shared__ int wsum[SCAN_BLK / 32];
    if (lane == 31) wsum[wid] = v;
    __syncthreads();
    if (threadIdx.x < SCAN_BLK / 32) {
        int s = wsum[threadIdx.x];
#pragma unroll
        for (int d = 1; d < SCAN_BLK / 32; d <<= 1) {
            int n = __shfl_up_sync(0xffu, s, d);
            if ((int)threadIdx.x >= d) s += n;
        }
        wsum[threadIdx.x] = s;
    }
    __syncthreads();
    int excl = v - c + (wid > 0 ? wsum[wid - 1] : 0) + g_blockOff[blockIdx.x];
    if (i < NODES) {
        g_rowptr[i] = excl;
        g_cursor[i] = excl;
    }
    if (blockIdx.x == 0 && threadIdx.x == 0) g_rowptr[NODES] = EDGES;
}

// ---------------- CSR fill (by dst), packed int2 ------------------------------
__global__ void csr_fill_kernel(const int* __restrict__ src, const int* __restrict__ dst,
                                const float* __restrict__ ew) {
    int e = blockIdx.x * blockDim.x + threadIdx.x;
    if (e < EDGES) {
        int d = dst[e];
        int p = atomicAdd(&g_cursor[d], 1);
        g_csr[p] = make_int2(src[e], __float_as_int(ew[e]));
    }
}

// ---------------- layer-1 tf32 GEMM: tb = bf16( (x*ns) @ W1 ) -----------------
// v2: 256 threads (8 warps), 64x64 tile, warp = 16 rows x 32 cols.
// Lower reg pressure -> higher occupancy -> hides DRAM latency streaming x.
__device__ __forceinline__ unsigned f2tf(float f) {
    unsigned u;
    asm("cvt.rna.tf32.f32 %0, %1;" : "=r"(u) : "f"(f));
    return u;
}

__device__ __forceinline__ void mma_tf32(float* d, const unsigned* a, const unsigned* b) {
    asm volatile(
        "mma.sync.aligned.m16n8k8.row.col.f32.tf32.tf32.f32 "
        "{%0,%1,%2,%3}, {%4,%5,%6,%7}, {%8,%9}, {%0,%1,%2,%3};\n"
        : "+f"(d[0]), "+f"(d[1]), "+f"(d[2]), "+f"(d[3])
        : "r"(a[0]), "r"(a[1]), "r"(a[2]), "r"(a[3]), "r"(b[0]), "r"(b[1]));
}

#define APAD 68  // 68 % 32 = 4 -> fragment loads hit all 32 banks (conflict-free)

__global__ void gemm1_kernel(const float* __restrict__ A, const float* __restrict__ W,
                             __nv_bfloat162* __restrict__ outb) {
    __shared__ unsigned sA[64 * APAD];
    __shared__ unsigned sB[64 * APAD];

    const int tid = threadIdx.x;            // 0..255
    const int wid = tid >> 5;               // 0..7
    const int lane = tid & 31;
    const int qr = lane >> 2;
    const int qc = lane & 3;
    const int warp_m = wid & 3;             // 4 m-warps, 16 rows each
    const int warp_n = wid >> 2;            // 2 n-warps, 32 cols each
    const int row0 = blockIdx.x * 64;

    float acc[4][4];
#pragma unroll
    for (int ni = 0; ni < 4; ni++)
#pragma unroll
        for (int j = 0; j < 4; j++) acc[ni][j] = 0.0f;

    for (int chunk = 0; chunk < INF; chunk += 64) {
        // ---- load+transform A: 1024 float4s across 256 threads (4 iters) ----
#pragma unroll
        for (int it = 0; it < 4; it++) {
            int idx4 = it * 256 + tid;
            int row = idx4 >> 4;
            int c4 = idx4 & 15;
            int grow = row0 + row;
            unsigned* dst = &sA[row * APAD + c4 * 4];
            if (grow < NODES) {
                float4 v = *(const float4*)&A[(long)grow * INF + chunk + c4 * 4];
                float ns = g_ns[grow];
                dst[0] = f2tf(v.x * ns);
                dst[1] = f2tf(v.y * ns);
                dst[2] = f2tf(v.z * ns);
                dst[3] = f2tf(v.w * ns);
            } else {
                dst[0] = 0u; dst[1] = 0u; dst[2] = 0u; dst[3] = 0u;
            }
        }
        // ---- transpose W chunk -> sB[n][k] (16 iters) ----
#pragma unroll
        for (int it = 0; it < 16; it++) {
            int idx = it * 256 + tid;
            int k = idx >> 6;
            int n = idx & 63;
            sB[n * APAD + k] = f2tf(W[(long)(chunk + k) * HF + n]);
        }
        __syncthreads();

#pragma unroll
        for (int kk8 = 0; kk8 < 8; kk8++) {
            const int kk = kk8 * 8;
            unsigned a[4], b[4][2];
            int r = warp_m * 16 + qr;
            a[0] = sA[r * APAD + kk + qc];
            a[1] = sA[(r + 8) * APAD + kk + qc];
            a[2] = sA[r * APAD + kk + qc + 4];
            a[3] = sA[(r + 8) * APAD + kk + qc + 4];
#pragma unroll
            for (int ni = 0; ni < 4; ni++) {
                int n = warp_n * 32 + ni * 8 + qr;
                b[ni][0] = sB[n * APAD + kk + qc];
                b[ni][1] = sB[n * APAD + kk + qc + 4];
            }
#pragma unroll
            for (int ni = 0; ni < 4; ni++)
                mma_tf32(acc[ni], a, b[ni]);
        }
        __syncthreads();
    }

    // ---- epilogue: pack to bf16x2 ----
    int r0 = row0 + warp_m * 16 + qr;
    int r1 = r0 + 8;
#pragma unroll
    for (int ni = 0; ni < 4; ni++) {
        int col2 = (warp_n * 32 + ni * 8 + qc * 2) >> 1;
        if (r0 < NODES)
            outb[(long)r0 * (HF / 2) + col2] = __floats2bfloat162_rn(acc[ni][0], acc[ni][1]);
        if (r1 < NODES)
            outb[(long)r1 * (HF / 2) + col2] = __floats2bfloat162_rn(acc[ni][2], acc[ni][3]);
    }
}

// ---------------- fused layer: agg(tb_in) -> transform -> bf16 GEMM -> tb_out -
// Block = 256 threads (8 warps), 64-row tile.
// Phase A: warp w aggregates nodes [row0+8w, row0+8w+8) with 8-edge MLP.
// Phase B: 64x64 GEMM h @ W via mma.m16n8k16 bf16; warp = 16 rows x 32 cols.
#define BPAD 72  // bf16 elems per row; 144B stride -> conflict-free frag loads

__device__ __forceinline__ void mma_bf16(float* d, const unsigned* a, const unsigned* b) {
    asm volatile(
        "mma.sync.aligned.m16n8k16.row.col.f32.bf16.bf16.f32 "
        "{%0,%1,%2,%3}, {%4,%5,%6,%7}, {%8,%9}, {%0,%1,%2,%3};\n"
        : "+f"(d[0]), "+f"(d[1]), "+f"(d[2]), "+f"(d[3])
        : "r"(a[0]), "r"(a[1]), "r"(a[2]), "r"(a[3]), "r"(b[0]), "r"(b[1]));
}

__global__ void fused_layer_kernel(const __nv_bfloat162* __restrict__ tb_in,
                                   const float* __restrict__ W,
                                   const float* __restrict__ bprev,
                                   __nv_bfloat162* __restrict__ tb_out) {
    __shared__ __nv_bfloat16 sA[64 * BPAD];  // [row][k]
    __shared__ __nv_bfloat16 sW[64 * BPAD];  // [n][k] (W transposed)

    const int tid = threadIdx.x;     // 0..255
    const int wid = tid >> 5;        // 0..7
    const int lane = tid & 31;
    const int row0 = blockIdx.x * 64;

    // load W transposed -> sW[n][k]
#pragma unroll
    for (int it = 0; it < 16; it++) {
        int idx = it * 256 + tid;    // 4096
        int k = idx >> 6;
        int n = idx & 63;
        sW[n * BPAD + k] = __float2bfloat16(W[k * HF + n]);
    }

    // Phase A: aggregate 8 nodes per warp, 8 edges in flight
    const float bx = bprev[2 * lane];
    const float by = bprev[2 * lane + 1];
#pragma unroll 1
    for (int r = 0; r < 8; r++) {
        int lrow = wid * 8 + r;
        int row = row0 + lrow;
        float a0 = 0.0f, a1 = 0.0f;
        if (row < NODES) {
            int beg = g_rowptr[row];
            int end = g_rowptr[row + 1];
            int j = beg;
            for (; j + 7 < end; j += 8) {
                int2 e[8];
                float2 f[8];
#pragma unroll
                for (int q = 0; q < 8; q++) e[q] = g_csr[j + q];
#pragma unroll
                for (int q = 0; q < 8; q++)
                    f[q] = __bfloat1622float2(tb_in[(long)e[q].x * (HF / 2) + lane]);
#pragma unroll
                for (int q = 0; q < 8; q++) {
                    float w = __int_as_float(e[q].y);
                    a0 = fmaf(f[q].x, w, a0);
                    a1 = fmaf(f[q].y, w, a1);
                }
            }
            for (; j < end; j++) {
                int2 e0 = g_csr[j];
                float2 f0 = __bfloat1622float2(tb_in[(long)e0.x * (HF / 2) + lane]);
                float w0 = __int_as_float(e0.y);
                a0 = fmaf(f0.x, w0, a0);
                a1 = fmaf(f0.y, w0, a1);
            }
            float nd = g_nd[row];
            float ns = g_ns[row];
            a0 = fmaxf(fmaf(a0, nd, bx), 0.0f) * ns;
            a1 = fmaxf(fmaf(a1, nd, by), 0.0f) * ns;
        }
        *(__nv_bfloat162*)&sA[lrow * BPAD + 2 * lane] = __floats2bfloat162_rn(a0, a1);
    }
    __syncthreads();

    // Phase B: GEMM sA @ sW^T; warp_m = wid&3 (16 rows), warp_n = wid>>2 (32 cols)
    const int warp_m = wid & 3;
    const int warp_n = wid >> 2;
    const int qr = lane >> 2;
    const int qc = lane & 3;

    float acc[4][4];
#pragma unroll
    for (int ni = 0; ni < 4; ni++)
#pragma unroll
        for (int j = 0; j < 4; j++) acc[ni][j] = 0.0f;

#pragma unroll
    for (int ks = 0; ks < 4; ks++) {
        const int kk = ks * 16;
        unsigned a[4], b[4][2];
        int ra = warp_m * 16 + qr;
        a[0] = *(const unsigned*)&sA[ra * BPAD + kk + 2 * qc];
        a[1] = *(const unsigned*)&sA[(ra + 8) * BPAD + kk + 2 * qc];
        a[2] = *(const unsigned*)&sA[ra * BPAD + kk + 2 * qc + 8];
        a[3] = *(const unsigned*)&sA[(ra + 8) * BPAD + kk + 2 * qc + 8];
#pragma unroll
        for (int ni = 0; ni < 4; ni++) {
            int n = warp_n * 32 + ni * 8 + qr;
            b[ni][0] = *(const unsigned*)&sW[n * BPAD + kk + 2 * qc];
            b[ni][1] = *(const unsigned*)&sW[n * BPAD + kk + 2 * qc + 8];
        }
#pragma unroll
        for (int ni = 0; ni < 4; ni++)
            mma_bf16(acc[ni], a, b[ni]);
    }

    // epilogue
    int r0 = row0 + warp_m * 16 + qr;
    int r1 = r0 + 8;
#pragma unroll
    for (int ni = 0; ni < 4; ni++) {
        int col2 = (warp_n * 32 + ni * 8 + qc * 2) >> 1;
        if (r0 < NODES)
            tb_out[(long)r0 * (HF / 2) + col2] = __floats2bfloat162_rn(acc[ni][0], acc[ni][1]);
        if (r1 < NODES)
            tb_out[(long)r1 * (HF / 2) + col2] = __floats2bfloat162_rn(acc[ni][2], acc[ni][3]);
    }
}

// ---------------- layer-3 agg + activate: aggf = relu(agg*nd + b3) ------------
__global__ void agg3_kernel(const __nv_bfloat162* __restrict__ tb,
                            const float* __restrict__ b3,
                            float* __restrict__ out) {
    int node = blockIdx.x * 8 + (threadIdx.x >> 5);
    if (node >= NODES) return;
    int lane = threadIdx.x & 31;
    int beg = g_rowptr[node];
    int end = g_rowptr[node + 1];
    float a0 = 0.0f, a1 = 0.0f;
    int j = beg;
    for (; j + 7 < end; j += 8) {
        int2 e[8];
        float2 f[8];
#pragma unroll
        for (int q = 0; q < 8; q++) e[q] = g_csr[j + q];
#pragma unroll
        for (int q = 0; q < 8; q++)
            f[q] = __bfloat1622float2(tb[(long)e[q].x * (HF / 2) + lane]);
#pragma unroll
        for (int q = 0; q < 8; q++) {
            float w = __int_as_float(e[q].y);
            a0 = fmaf(f[q].x, w, a0);
            a1 = fmaf(f[q].y, w, a1);
        }
    }
    for (; j < end; j++) {
        int2 e0 = g_csr[j];
        float2 f0 = __bfloat1622float2(tb[(long)e0.x * (HF / 2) + lane]);
        float w0 = __int_as_float(e0.y);
        a0 = fmaf(f0.x, w0, a0);
        a1 = fmaf(f0.y, w0, a1);
    }
    float nd = g_nd[node];
    float r0 = fmaxf(fmaf(a0, nd, b3[2 * lane]), 0.0f);
    float r1 = fmaxf(fmaf(a1, nd, b3[2 * lane + 1]), 0.0f);
    *(float2*)&out[(long)node * HF + 2 * lane] = make_float2(r0, r1);
}

// ---------------- pool (mean per graph) + MLP head + sigmoid ------------------
__device__ __forceinline__ int lower_bound_dev(const int* __restrict__ a, int n, int key) {
    int lo = 0, hi = n;
    while (lo < hi) {
        int mid = (lo + hi) >> 1;
        if (a[mid] < key) lo = mid + 1; else hi = mid;
    }
    return lo;
}

__global__ void pool_mlp_kernel(const float* __restrict__ aggf,
                                const int* __restrict__ gid,
                                const float* __restrict__ Dw1, const float* __restrict__ Db1,
                                const float* __restrict__ Dw2, const float* __restrict__ Db2,
                                const float* __restrict__ Dw3, const float* __restrict__ Db3,
                                float* __restrict__ out) {
    int g = blockIdx.x;
    int t = threadIdx.x;  // 64 threads
    int start = lower_bound_dev(gid, NODES, g);
    int end = lower_bound_dev(gid, NODES, g + 1);

    float sum = 0.0f;
    for (int n = start; n < end; n++) sum += aggf[(long)n * HF + t];
    float cnt = fmaxf((float)(end - start), 1.0f);

    __shared__ float pooled[64];
    __shared__ float h1[16];
    __shared__ float h2[8];
    pooled[t] = sum / cnt;
    __syncthreads();

    if (t < 16) {
        float s = Db1[t];
#pragma unroll
        for (int k = 0; k < 64; k++) s = fmaf(pooled[k], Dw1[k * 16 + t], s);
        h1[t] = fmaxf(s, 0.0f);
    }
    __syncthreads();
    if (t < 8) {
        float s = Db2[t];
#pragma unroll
        for (int k = 0; k < 16; k++) s = fmaf(h1[k], Dw2[k * 8 + t], s);
        h2[t] = fmaxf(s, 0.0f);
    }
    __syncthreads();
    if (t == 0) {
        float s = Db3[0];
#pragma unroll
        for (int k = 0; k < 8; k++) s = fmaf(h2[k], Dw3[k], s);
        out[g] = 1.0f / (1.0f + expf(-s));
    }
}

// ---------------- launch ------------------------------------------------------
extern "C" void kernel_launch(void* const* d_in, const int* in_sizes, int n_in,
                              void* d_out, int out_size) {
    const float* x   = (const float*)d_in[0];
    const int*   src = (const int*)d_in[1];
    const int*   dst = (const int*)d_in[2];
    const float* ew  = (const float*)d_in[3];
    const int*   gid = (const int*)d_in[4];
    const float* W1  = (const float*)d_in[5];
    const float* b1  = (const float*)d_in[6];
    const float* W2  = (const float*)d_in[7];
    const float* b2  = (const float*)d_in[8];
    const float* W3  = (const float*)d_in[9];
    const float* b3  = (const float*)d_in[10];
    const float* Dw1 = (const float*)d_in[11];
    const float* Db1 = (const float*)d_in[12];
    const float* Dw2 = (const float*)d_in[13];
    const float* Db2 = (const float*)d_in[14];
    const float* Dw3 = (const float*)d_in[15];
    const float* Db3 = (const float*)d_in[16];
    float* out = (float*)d_out;

    __nv_bfloat162* tb_ptr; cudaGetSymbolAddress((void**)&tb_ptr, g_tb);
    float* aggf_ptr;        cudaGetSymbolAddress((void**)&aggf_ptr, g_aggf);

    const int NB = (NODES + 255) / 256;
    const int EB = (EDGES + 255) / 256;
    const int GB = (NODES + 63) / 64;   // 64-row tiles
    const int AB = (NODES + 7) / 8;     // agg blocks (8 warps each)

    // 1-3: degree + norms (gemm1 needs only ns)
    zero_counts_kernel<<<NB, 256>>>();
    degree_kernel<<<EB, 256>>>(src, dst);
    norm_kernel<<<NB, 256>>>();

    // 4: layer-1 GEMM (profiled slot)
    gemm1_kernel<<<GB, 256>>>(x, W1, tb_ptr);

    // 5-8: CSR build
    scan1_kernel<<<NBLK, SCAN_BLK>>>();
    scan2_kernel<<<1, 512>>>();
    scan3_kernel<<<NBLK, SCAN_BLK>>>();
    csr_fill_kernel<<<EB, 256>>>(src, dst, ew);

    // 9-10: fused agg+transform+GEMM for layers 2 and 3
    fused_layer_kernel<<<GB, 256>>>(tb_ptr, W2, b1, tb_ptr);
    fused_layer_kernel<<<GB, 256>>>(tb_ptr, W3, b2, tb_ptr);

    // 11: layer-3 aggregation + activation
    agg3_kernel<<<AB, 256>>>(tb_ptr, b3, aggf_ptr);

    // 12: pool + MLP + sigmoid
    pool_mlp_kernel<<<GRAPHS, 64>>>(aggf_ptr, gid, Dw1, Db1, Dw2, Db2, Dw3, Db3, out);
}

// round 9
// speedup vs baseline: 2.2571x; 1.0632x over previous
#include <cuda_runtime.h>
#include <cuda_bf16.h>
#include <math.h>

// Problem constants (fixed by the dataset)
#define NODES 100000
#define EDGES 1600000
#define GRAPHS 256
#define INF 128
#define HF 64
#define SCAN_BLK 256
#define NBLK ((NODES + SCAN_BLK - 1) / SCAN_BLK)   // 391

// ---------------- scratch (static device globals; no allocation) -------------
__device__ int   g_cnt_out[NODES];
__device__ int   g_cnt_in[NODES];
__device__ float g_ns[NODES];
__device__ float g_nd[NODES];
__device__ int   g_rowptr[NODES + 1];
__device__ int   g_cursor[NODES];
__device__ int2  g_csr[EDGES];                     // {src, w-bits}
__device__ int   g_blockSums[NBLK];
__device__ int   g_blockOff[NBLK];
__device__ __nv_bfloat162 g_tb[NODES * (HF / 2)];  // per-layer GEMM output (bf16x2)
__device__ float g_aggf[NODES * HF];               // layer-3 activated output (fp32)

// ---------------- init: zero degree counters ---------------------------------
__global__ void zero_counts_kernel() {
    int i = blockIdx.x * blockDim.x + threadIdx.x;
    if (i < NODES) { g_cnt_out[i] = 0; g_cnt_in[i] = 0; }
}

// ---------------- degree histogram -------------------------------------------
__global__ void degree_kernel(const int* __restrict__ src, const int* __restrict__ dst) {
    int e = blockIdx.x * blockDim.x + threadIdx.x;
    if (e < EDGES) {
        atomicAdd(&g_cnt_out[src[e]], 1);
        atomicAdd(&g_cnt_in[dst[e]], 1);
    }
}

// ---------------- norms (needs only degree counts) ----------------------------
__global__ void norm_kernel() {
    int i = blockIdx.x * blockDim.x + threadIdx.x;
    if (i < NODES) {
        g_ns[i] = rsqrtf(fmaxf((float)g_cnt_out[i], 1.0f));
        g_nd[i] = rsqrtf(fmaxf((float)g_cnt_in[i], 1.0f));
    }
}

// ---------------- 3-phase parallel scan of deg_in -----------------------------
__global__ void scan1_kernel() {
    int i = blockIdx.x * SCAN_BLK + threadIdx.x;
    int c = (i < NODES) ? g_cnt_in[i] : 0;
#pragma unroll
    for (int d = 16; d; d >>= 1) c += __shfl_down_sync(0xffffffffu, c, d);
    __shared__ int w[SCAN_BLK / 32];
    if ((threadIdx.x & 31) == 0) w[threadIdx.x >> 5] = c;
    __syncthreads();
    if (threadIdx.x < SCAN_BLK / 32) {
        int s = w[threadIdx.x];
#pragma unroll
        for (int d = SCAN_BLK / 64; d; d >>= 1) s += __shfl_down_sync(0xffu, s, d);
        if (threadIdx.x == 0) g_blockSums[blockIdx.x] = s;
    }
}

__global__ void scan2_kernel() {
    __shared__ int ss[512];
    int t = threadIdx.x;
    int v = (t < NBLK) ? g_blockSums[t] : 0;
    ss[t] = v;
    __syncthreads();
    for (int d = 1; d < 512; d <<= 1) {
        int o = (t >= d) ? ss[t - d] : 0;
        __syncthreads();
        ss[t] += o;
        __syncthreads();
    }
    if (t < NBLK) g_blockOff[t] = ss[t] - v;  // exclusive
}

__global__ void scan3_kernel() {
    int i = blockIdx.x * SCAN_BLK + threadIdx.x;
    int c = (i < NODES) ? g_cnt_in[i] : 0;
    int lane = threadIdx.x & 31, wid = threadIdx.x >> 5;
    int v = c;
#pragma unroll
    for (int d = 1; d < 32; d <<= 1) {
        int n = __shfl_up_sync(0xffffffffu, v, d);
        if (lane >= d) v += n;
    }
    __shared__ int wsum[SCAN_BLK / 32];
    if (lane == 31) wsum[wid] = v;
    __syncthreads();
    if (threadIdx.x < SCAN_BLK / 32) {
        int s = wsum[threadIdx.x];
#pragma unroll
        for (int d = 1; d < SCAN_BLK / 32; d <<= 1) {
            int n = __shfl_up_sync(0xffu, s, d);
            if ((int)threadIdx.x >= d) s += n;
        }
        wsum[threadIdx.x] = s;
    }
    __syncthreads();
    int excl = v - c + (wid > 0 ? wsum[wid - 1] : 0) + g_blockOff[blockIdx.x];
    if (i < NODES) {
        g_rowptr[i] = excl;
        g_cursor[i] = excl;
    }
    if (blockIdx.x == 0 && threadIdx.x == 0) g_rowptr[NODES] = EDGES;
}

// ---------------- CSR fill (by dst), packed int2 ------------------------------
__global__ void csr_fill_kernel(const int* __restrict__ src, const int* __restrict__ dst,
                                const float* __restrict__ ew) {
    int e = blockIdx.x * blockDim.x + threadIdx.x;
    if (e < EDGES) {
        int d = dst[e];
        int p = atomicAdd(&g_cursor[d], 1);
        g_csr[p] = make_int2(src[e], __float_as_int(ew[e]));
    }
}

// ---------------- layer-1 tf32 GEMM: tb = bf16( ns * (x @ W1) ) ---------------
// v3: 256 threads, 64x64 tile. Full 64x128 A tile prefetched into registers
// (8 LDG.128/thread, MLP=8) before any smem traffic; ns applied in epilogue.
__device__ __forceinline__ unsigned f2tf(float f) {
    unsigned u;
    asm("cvt.rna.tf32.f32 %0, %1;" : "=r"(u) : "f"(f));
    return u;
}

__device__ __forceinline__ void mma_tf32(float* d, const unsigned* a, const unsigned* b) {
    asm volatile(
        "mma.sync.aligned.m16n8k8.row.col.f32.tf32.tf32.f32 "
        "{%0,%1,%2,%3}, {%4,%5,%6,%7}, {%8,%9}, {%0,%1,%2,%3};\n"
        : "+f"(d[0]), "+f"(d[1]), "+f"(d[2]), "+f"(d[3])
        : "r"(a[0]), "r"(a[1]), "r"(a[2]), "r"(a[3]), "r"(b[0]), "r"(b[1]));
}

#define APAD 68  // 68 % 32 = 4 -> fragment loads hit all 32 banks (conflict-free)

__global__ void gemm1_kernel(const float* __restrict__ A, const float* __restrict__ W,
                             __nv_bfloat162* __restrict__ outb) {
    __shared__ unsigned sA[64 * APAD];
    __shared__ unsigned sB[64 * APAD];

    const int tid = threadIdx.x;            // 0..255
    const int wid = tid >> 5;               // 0..7
    const int lane = tid & 31;
    const int qr = lane >> 2;
    const int qc = lane & 3;
    const int warp_m = wid & 3;             // 4 m-warps, 16 rows each
    const int warp_n = wid >> 2;            // 2 n-warps, 32 cols each
    const int row0 = blockIdx.x * 64;

    // ---- prefetch entire 64x128 A tile: 2048 float4s / 256 threads = 8 each --
    float4 va[8];
#pragma unroll
    for (int it = 0; it < 8; it++) {
        int idx4 = it * 256 + tid;          // 0..2047
        int row = idx4 >> 5;                // 32 float4 per row
        int c4 = idx4 & 31;
        int grow = row0 + row;
        va[it] = (grow < NODES) ? *(const float4*)&A[(long)grow * INF + c4 * 4]
                                : make_float4(0.f, 0.f, 0.f, 0.f);
    }

    float acc[4][4];
#pragma unroll
    for (int ni = 0; ni < 4; ni++)
#pragma unroll
        for (int j = 0; j < 4; j++) acc[ni][j] = 0.0f;

#pragma unroll
    for (int chunk = 0; chunk < 2; chunk++) {
        // ---- W chunk -> sB transposed (L1-hot after first wave) ----
#pragma unroll
        for (int it = 0; it < 16; it++) {
            int idx = it * 256 + tid;       // 4096 elements
            int k = idx >> 6;
            int n = idx & 63;
            sB[n * APAD + k] = f2tf(W[(long)(chunk * 64 + k) * HF + n]);
        }
        // ---- A chunk from registers -> sA ----
#pragma unroll
        for (int it = 0; it < 8; it++) {
            int idx4 = it * 256 + tid;
            int row = idx4 >> 5;
            int c4 = idx4 & 31;
            if ((c4 >> 4) == chunk) {
                int c4m = c4 & 15;
                unsigned* d = &sA[row * APAD + c4m * 4];
                d[0] = f2tf(va[it].x);
                d[1] = f2tf(va[it].y);
                d[2] = f2tf(va[it].z);
                d[3] = f2tf(va[it].w);
            }
        }
        __syncthreads();

#pragma unroll
        for (int kk8 = 0; kk8 < 8; kk8++) {
            const int kk = kk8 * 8;
            unsigned a[4], b[4][2];
            int r = warp_m * 16 + qr;
            a[0] = sA[r * APAD + kk + qc];
            a[1] = sA[(r + 8) * APAD + kk + qc];
            a[2] = sA[r * APAD + kk + qc + 4];
            a[3] = sA[(r + 8) * APAD + kk + qc + 4];
#pragma unroll
            for (int ni = 0; ni < 4; ni++) {
                int n = warp_n * 32 + ni * 8 + qr;
                b[ni][0] = sB[n * APAD + kk + qc];
                b[ni][1] = sB[n * APAD + kk + qc + 4];
            }
#pragma unroll
            for (int ni = 0; ni < 4; ni++)
                mma_tf32(acc[ni], a, b[ni]);
        }
        __syncthreads();
    }

    // ---- epilogue: row-scale by ns, pack to bf16x2 ----
    int r0 = row0 + warp_m * 16 + qr;
    int r1 = r0 + 8;
    float ns0 = (r0 < NODES) ? g_ns[r0] : 0.0f;
    float ns1 = (r1 < NODES) ? g_ns[r1] : 0.0f;
#pragma unroll
    for (int ni = 0; ni < 4; ni++) {
        int col2 = (warp_n * 32 + ni * 8 + qc * 2) >> 1;
        if (r0 < NODES)
            outb[(long)r0 * (HF / 2) + col2] =
                __floats2bfloat162_rn(acc[ni][0] * ns0, acc[ni][1] * ns0);
        if (r1 < NODES)
            outb[(long)r1 * (HF / 2) + col2] =
                __floats2bfloat162_rn(acc[ni][2] * ns1, acc[ni][3] * ns1);
    }
}

// ---------------- fused layer: agg(tb_in) -> transform -> bf16 GEMM -> tb_out -
#define BPAD 72  // bf16 elems per row; 144B stride -> conflict-free frag loads

__device__ __forceinline__ void mma_bf16(float* d, const unsigned* a, const unsigned* b) {
    asm volatile(
        "mma.sync.aligned.m16n8k16.row.col.f32.bf16.bf16.f32 "
        "{%0,%1,%2,%3}, {%4,%5,%6,%7}, {%8,%9}, {%0,%1,%2,%3};\n"
        : "+f"(d[0]), "+f"(d[1]), "+f"(d[2]), "+f"(d[3])
        : "r"(a[0]), "r"(a[1]), "r"(a[2]), "r"(a[3]), "r"(b[0]), "r"(b[1]));
}

__global__ void fused_layer_kernel(const __nv_bfloat162* __restrict__ tb_in,
                                   const float* __restrict__ W,
                                   const float* __restrict__ bprev,
                                   __nv_bfloat162* __restrict__ tb_out) {
    __shared__ __nv_bfloat16 sA[64 * BPAD];  // [row][k]
    __shared__ __nv_bfloat16 sW[64 * BPAD];  // [n][k] (W transposed)

    const int tid = threadIdx.x;     // 0..255
    const int wid = tid >> 5;        // 0..7
    const int lane = tid & 31;
    const int row0 = blockIdx.x * 64;

    // load W transposed -> sW[n][k]
#pragma unroll
    for (int it = 0; it < 16; it++) {
        int idx = it * 256 + tid;    // 4096
        int k = idx >> 6;
        int n = idx & 63;
        sW[n * BPAD + k] = __float2bfloat16(W[k * HF + n]);
    }

    // Phase A: aggregate 8 nodes per warp, 8 edges in flight
    const float bx = bprev[2 * lane];
    const float by = bprev[2 * lane + 1];
#pragma unroll 1
    for (int r = 0; r < 8; r++) {
        int lrow = wid * 8 + r;
        int row = row0 + lrow;
        float a0 = 0.0f, a1 = 0.0f;
        if (row < NODES) {
            int beg = g_rowptr[row];
            int end = g_rowptr[row + 1];
            int j = beg;
            for (; j + 7 < end; j += 8) {
                int2 e[8];
                float2 f[8];
#pragma unroll
                for (int q = 0; q < 8; q++) e[q] = g_csr[j + q];
#pragma unroll
                for (int q = 0; q < 8; q++)
                    f[q] = __bfloat1622float2(tb_in[(long)e[q].x * (HF / 2) + lane]);
#pragma unroll
                for (int q = 0; q < 8; q++) {
                    float w = __int_as_float(e[q].y);
                    a0 = fmaf(f[q].x, w, a0);
                    a1 = fmaf(f[q].y, w, a1);
                }
            }
            for (; j < end; j++) {
                int2 e0 = g_csr[j];
                float2 f0 = __bfloat1622float2(tb_in[(long)e0.x * (HF / 2) + lane]);
                float w0 = __int_as_float(e0.y);
                a0 = fmaf(f0.x, w0, a0);
                a1 = fmaf(f0.y, w0, a1);
            }
            float nd = g_nd[row];
            float ns = g_ns[row];
            a0 = fmaxf(fmaf(a0, nd, bx), 0.0f) * ns;
            a1 = fmaxf(fmaf(a1, nd, by), 0.0f) * ns;
        }
        *(__nv_bfloat162*)&sA[lrow * BPAD + 2 * lane] = __floats2bfloat162_rn(a0, a1);
    }
    __syncthreads();

    // Phase B: GEMM sA @ sW^T
    const int warp_m = wid & 3;
    const int warp_n = wid >> 2;
    const int qr = lane >> 2;
    const int qc = lane & 3;

    float acc[4][4];
#pragma unroll
    for (int ni = 0; ni < 4; ni++)
#pragma unroll
        for (int j = 0; j < 4; j++) acc[ni][j] = 0.0f;

#pragma unroll
    for (int ks = 0; ks < 4; ks++) {
        const int kk = ks * 16;
        unsigned a[4], b[4][2];
        int ra = warp_m * 16 + qr;
        a[0] = *(const unsigned*)&sA[ra * BPAD + kk + 2 * qc];
        a[1] = *(const unsigned*)&sA[(ra + 8) * BPAD + kk + 2 * qc];
        a[2] = *(const unsigned*)&sA[ra * BPAD + kk + 2 * qc + 8];
        a[3] = *(const unsigned*)&sA[(ra + 8) * BPAD + kk + 2 * qc + 8];
#pragma unroll
        for (int ni = 0; ni < 4; ni++) {
            int n = warp_n * 32 + ni * 8 + qr;
            b[ni][0] = *(const unsigned*)&sW[n * BPAD + kk + 2 * qc];
            b[ni][1] = *(const unsigned*)&sW[n * BPAD + kk + 2 * qc + 8];
        }
#pragma unroll
        for (int ni = 0; ni < 4; ni++)
            mma_bf16(acc[ni], a, b[ni]);
    }

    // epilogue
    int r0 = row0 + warp_m * 16 + qr;
    int r1 = r0 + 8;
#pragma unroll
    for (int ni = 0; ni < 4; ni++) {
        int col2 = (warp_n * 32 + ni * 8 + qc * 2) >> 1;
        if (r0 < NODES)
            tb_out[(long)r0 * (HF / 2) + col2] = __floats2bfloat162_rn(acc[ni][0], acc[ni][1]);
        if (r1 < NODES)
            tb_out[(long)r1 * (HF / 2) + col2] = __floats2bfloat162_rn(acc[ni][2], acc[ni][3]);
    }
}

// ---------------- layer-3 agg + activate: aggf = relu(agg*nd + b3) ------------
__global__ void agg3_kernel(const __nv_bfloat162* __restrict__ tb,
                            const float* __restrict__ b3,
                            float* __restrict__ out) {
    int node = blockIdx.x * 8 + (threadIdx.x >> 5);
    if (node >= NODES) return;
    int lane = threadIdx.x & 31;
    int beg = g_rowptr[node];
    int end = g_rowptr[node + 1];
    float a0 = 0.0f, a1 = 0.0f;
    int j = beg;
    for (; j + 7 < end; j += 8) {
        int2 e[8];
        float2 f[8];
#pragma unroll
        for (int q = 0; q < 8; q++) e[q] = g_csr[j + q];
#pragma unroll
        for (int q = 0; q < 8; q++)
            f[q] = __bfloat1622float2(tb[(long)e[q].x * (HF / 2) + lane]);
#pragma unroll
        for (int q = 0; q < 8; q++) {
            float w = __int_as_float(e[q].y);
            a0 = fmaf(f[q].x, w, a0);
            a1 = fmaf(f[q].y, w, a1);
        }
    }
    for (; j < end; j++) {
        int2 e0 = g_csr[j];
        float2 f0 = __bfloat1622float2(tb[(long)e0.x * (HF / 2) + lane]);
        float w0 = __int_as_float(e0.y);
        a0 = fmaf(f0.x, w0, a0);
        a1 = fmaf(f0.y, w0, a1);
    }
    float nd = g_nd[node];
    float r0 = fmaxf(fmaf(a0, nd, b3[2 * lane]), 0.0f);
    float r1 = fmaxf(fmaf(a1, nd, b3[2 * lane + 1]), 0.0f);
    *(float2*)&out[(long)node * HF + 2 * lane] = make_float2(r0, r1);
}

// ---------------- pool (mean per graph) + MLP head + sigmoid ------------------
__device__ __forceinline__ int lower_bound_dev(const int* __restrict__ a, int n, int key) {
    int lo = 0, hi = n;
    while (lo < hi) {
        int mid = (lo + hi) >> 1;
        if (a[mid] < key) lo = mid + 1; else hi = mid;
    }
    return lo;
}

__global__ void pool_mlp_kernel(const float* __restrict__ aggf,
                                const int* __restrict__ gid,
                                const float* __restrict__ Dw1, const float* __restrict__ Db1,
                                const float* __restrict__ Dw2, const float* __restrict__ Db2,
                                const float* __restrict__ Dw3, const float* __restrict__ Db3,
                                float* __restrict__ out) {
    int g = blockIdx.x;
    int t = threadIdx.x;  // 64 threads
    int start = lower_bound_dev(gid, NODES, g);
    int end = lower_bound_dev(gid, NODES, g + 1);

    float sum = 0.0f;
    for (int n = start; n < end; n++) sum += aggf[(long)n * HF + t];
    float cnt = fmaxf((float)(end - start), 1.0f);

    __shared__ float pooled[64];
    __shared__ float h1[16];
    __shared__ float h2[8];
    pooled[t] = sum / cnt;
    __syncthreads();

    if (t < 16) {
        float s = Db1[t];
#pragma unroll
        for (int k = 0; k < 64; k++) s = fmaf(pooled[k], Dw1[k * 16 + t], s);
        h1[t] = fmaxf(s, 0.0f);
    }
    __syncthreads();
    if (t < 8) {
        float s = Db2[t];
#pragma unroll
        for (int k = 0; k < 16; k++) s = fmaf(h1[k], Dw2[k * 8 + t], s);
        h2[t] = fmaxf(s, 0.0f);
    }
    __syncthreads();
    if (t == 0) {
        float s = Db3[0];
#pragma unroll
        for (int k = 0; k < 8; k++) s = fmaf(h2[k], Dw3[k], s);
        out[g] = 1.0f / (1.0f + expf(-s));
    }
}

// ---------------- launch ------------------------------------------------------
extern "C" void kernel_launch(void* const* d_in, const int* in_sizes, int n_in,
                              void* d_out, int out_size) {
    const float* x   = (const float*)d_in[0];
    const int*   src = (const int*)d_in[1];
    const int*   dst = (const int*)d_in[2];
    const float* ew  = (const float*)d_in[3];
    const int*   gid = (const int*)d_in[4];
    const float* W1  = (const float*)d_in[5];
    const float* b1  = (const float*)d_in[6];
    const float* W2  = (const float*)d_in[7];
    const float* b2  = (const float*)d_in[8];
    const float* W3  = (const float*)d_in[9];
    const float* b3  = (const float*)d_in[10];
    const float* Dw1 = (const float*)d_in[11];
    const float* Db1 = (const float*)d_in[12];
    const float* Dw2 = (const float*)d_in[13];
    const float* Db2 = (const float*)d_in[14];
    const float* Dw3 = (const float*)d_in[15];
    const float* Db3 = (const float*)d_in[16];
    float* out = (float*)d_out;

    __nv_bfloat162* tb_ptr; cudaGetSymbolAddress((void**)&tb_ptr, g_tb);
    float* aggf_ptr;        cudaGetSymbolAddress((void**)&aggf_ptr, g_aggf);

    const int NB = (NODES + 255) / 256;
    const int EB = (EDGES + 255) / 256;
    const int GB = (NODES + 63) / 64;   // 64-row tiles
    const int AB = (NODES + 7) / 8;     // agg blocks (8 warps each)

    // Side stream + events for CSR-build overlap (created once, on the first
    // call, which is the non-captured correctness run; reused during capture).
    static cudaStream_t s2 = nullptr;
    static cudaEvent_t evA = nullptr, evB = nullptr;
    if (s2 == nullptr) {
        if (cudaStreamCreateWithFlags(&s2, cudaStreamNonBlocking) != cudaSuccess) s2 = nullptr;
        if (s2) {
            if (cudaEventCreateWithFlags(&evA, cudaEventDisableTiming) != cudaSuccess ||
                cudaEventCreateWithFlags(&evB, cudaEventDisableTiming) != cudaSuccess) {
                s2 = nullptr;
            }
        }
    }

    // 1-2: degree histogram (common dependency)
    zero_counts_kernel<<<NB, 256>>>();
    degree_kernel<<<EB, 256>>>(src, dst);

    if (s2) {
        // fork: CSR build on s2, norms+gemm1 on main — independent given degrees
        cudaEventRecord(evA, 0);
        cudaStreamWaitEvent(s2, evA, 0);

        norm_kernel<<<NB, 256>>>();
        gemm1_kernel<<<GB, 256>>>(x, W1, tb_ptr);

        scan1_kernel<<<NBLK, SCAN_BLK, 0, s2>>>();
        scan2_kernel<<<1, 512, 0, s2>>>();
        scan3_kernel<<<NBLK, SCAN_BLK, 0, s2>>>();
        csr_fill_kernel<<<EB, 256, 0, s2>>>(src, dst, ew);
        cudaEventRecord(evB, s2);
        cudaStreamWaitEvent(0, evB, 0);
    } else {
        // sequential fallback
        norm_kernel<<<NB, 256>>>();
        gemm1_kernel<<<GB, 256>>>(x, W1, tb_ptr);
        scan1_kernel<<<NBLK, SCAN_BLK>>>();
        scan2_kernel<<<1, 512>>>();
        scan3_kernel<<<NBLK, SCAN_BLK>>>();
        csr_fill_kernel<<<EB, 256>>>(src, dst, ew);
    }

    // fused agg+transform+GEMM for layers 2 and 3
    fused_layer_kernel<<<GB, 256>>>(tb_ptr, W2, b1, tb_ptr);
    fused_layer_kernel<<<GB, 256>>>(tb_ptr, W3, b2, tb_ptr);

    // layer-3 aggregation + activation
    agg3_kernel<<<AB, 256>>>(tb_ptr, b3, aggf_ptr);

    // pool + MLP + sigmoid
    pool_mlp_kernel<<<GRAPHS, 64>>>(aggf_ptr, gid, Dw1, Db1, Dw2, Db2, Dw3, Db3, out);
}

// round 10
// speedup vs baseline: 2.4751x; 1.0966x over previous
#include <cuda_runtime.h>
#include <cuda_bf16.h>
#include <math.h>

// Problem constants (fixed by the dataset)
#define NODES 100000
#define EDGES 1600000
#define GRAPHS 256
#define INF 128
#define HF 64
#define SCAN_BLK 256
#define NBLK ((NODES + SCAN_BLK - 1) / SCAN_BLK)   // 391

// ---------------- scratch (static device globals; no allocation) -------------
__device__ int   g_cnt_out[NODES];
__device__ int   g_cnt_in[NODES];
__device__ float g_ns[NODES];
__device__ float g_nd[NODES];
__device__ int   g_rowptr[NODES + 1];
__device__ int   g_cursor[NODES];
__device__ int2  g_csr[EDGES];                     // {src, w-bits}
__device__ int   g_blockSums[NBLK];
__device__ int   g_blockOff[NBLK];
__device__ __nv_bfloat162 g_tb[NODES * (HF / 2)];  // per-layer GEMM output (bf16x2)
__device__ float g_aggf[NODES * HF];               // layer-3 activated output (fp32)

// ---------------- init: zero degree counters ---------------------------------
__global__ void zero_counts_kernel() {
    int i = blockIdx.x * blockDim.x + threadIdx.x;
    if (i < NODES) { g_cnt_out[i] = 0; g_cnt_in[i] = 0; }
}

// ---------------- degree histogram -------------------------------------------
__global__ void degree_kernel(const int* __restrict__ src, const int* __restrict__ dst) {
    int e = blockIdx.x * blockDim.x + threadIdx.x;
    if (e < EDGES) {
        atomicAdd(&g_cnt_out[src[e]], 1);
        atomicAdd(&g_cnt_in[dst[e]], 1);
    }
}

// ---------------- norms (needs only degree counts) ----------------------------
__global__ void norm_kernel() {
    int i = blockIdx.x * blockDim.x + threadIdx.x;
    if (i < NODES) {
        g_ns[i] = rsqrtf(fmaxf((float)g_cnt_out[i], 1.0f));
        g_nd[i] = rsqrtf(fmaxf((float)g_cnt_in[i], 1.0f));
    }
}

// ---------------- 3-phase parallel scan of deg_in -----------------------------
__global__ void scan1_kernel() {
    int i = blockIdx.x * SCAN_BLK + threadIdx.x;
    int c = (i < NODES) ? g_cnt_in[i] : 0;
#pragma unroll
    for (int d = 16; d; d >>= 1) c += __shfl_down_sync(0xffffffffu, c, d);
    __shared__ int w[SCAN_BLK / 32];
    if ((threadIdx.x & 31) == 0) w[threadIdx.x >> 5] = c;
    __syncthreads();
    if (threadIdx.x < SCAN_BLK / 32) {
        int s = w[threadIdx.x];
#pragma unroll
        for (int d = SCAN_BLK / 64; d; d >>= 1) s += __shfl_down_sync(0xffu, s, d);
        if (threadIdx.x == 0) g_blockSums[blockIdx.x] = s;
    }
}

__global__ void scan2_kernel() {
    __shared__ int ss[512];
    int t = threadIdx.x;
    int v = (t < NBLK) ? g_blockSums[t] : 0;
    ss[t] = v;
    __syncthreads();
    for (int d = 1; d < 512; d <<= 1) {
        int o = (t >= d) ? ss[t - d] : 0;
        __syncthreads();
        ss[t] += o;
        __syncthreads();
    }
    if (t < NBLK) g_blockOff[t] = ss[t] - v;  // exclusive
}

__global__ void scan3_kernel() {
    int i = blockIdx.x * SCAN_BLK + threadIdx.x;
    int c = (i < NODES) ? g_cnt_in[i] : 0;
    int lane = threadIdx.x & 31, wid = threadIdx.x >> 5;
    int v = c;
#pragma unroll
    for (int d = 1; d < 32; d <<= 1) {
        int n = __shfl_up_sync(0xffffffffu, v, d);
        if (lane >= d) v += n;
    }
    __shared__ int wsum[SCAN_BLK / 32];
    if (lane == 31) wsum[wid] = v;
    __syncthreads();
    if (threadIdx.x < SCAN_BLK / 32) {
        int s = wsum[threadIdx.x];
#pragma unroll
        for (int d = 1; d < SCAN_BLK / 32; d <<= 1) {
            int n = __shfl_up_sync(0xffu, s, d);
            if ((int)threadIdx.x >= d) s += n;
        }
        wsum[threadIdx.x] = s;
    }
    __syncthreads();
    int excl = v - c + (wid > 0 ? wsum[wid - 1] : 0) + g_blockOff[blockIdx.x];
    if (i < NODES) {
        g_rowptr[i] = excl;
        g_cursor[i] = excl;
    }
    if (blockIdx.x == 0 && threadIdx.x == 0) g_rowptr[NODES] = EDGES;
}

// ---------------- CSR fill (by dst), packed int2 ------------------------------
__global__ void csr_fill_kernel(const int* __restrict__ src, const int* __restrict__ dst,
                                const float* __restrict__ ew) {
    int e = blockIdx.x * blockDim.x + threadIdx.x;
    if (e < EDGES) {
        int d = dst[e];
        int p = atomicAdd(&g_cursor[d], 1);
        g_csr[p] = make_int2(src[e], __float_as_int(ew[e]));
    }
}

// ---------------- layer-1 tf32 GEMM: tb = bf16( ns * (x @ W1) ) ---------------
// v4: cp.async full-tile staging (one wait), raw fp32 bits fed as tf32,
// W kept [k][n] in smem (no transpose; stride 68 keeps frag loads conflict-free).
#define ASTRIDE 132  // fp32 per A row (128 + 4): a-frag bank = 4*qr+qc
#define BSTRIDE 68   // fp32 per W row (64 + 4):  b-frag bank = 4*qc+qr
#define GEMM1_SMEM ((64 * ASTRIDE + 128 * BSTRIDE) * 4)  // 68608 B

__device__ __forceinline__ void mma_tf32(float* d, const unsigned* a, const unsigned* b) {
    asm volatile(
        "mma.sync.aligned.m16n8k8.row.col.f32.tf32.tf32.f32 "
        "{%0,%1,%2,%3}, {%4,%5,%6,%7}, {%8,%9}, {%0,%1,%2,%3};\n"
        : "+f"(d[0]), "+f"(d[1]), "+f"(d[2]), "+f"(d[3])
        : "r"(a[0]), "r"(a[1]), "r"(a[2]), "r"(a[3]), "r"(b[0]), "r"(b[1]));
}

__device__ __forceinline__ void cp_async16(void* smem_dst, const void* gmem_src, int srcBytes) {
    unsigned saddr = (unsigned)__cvta_generic_to_shared(smem_dst);
    asm volatile("cp.async.cg.shared.global [%0], [%1], 16, %2;"
                 :: "r"(saddr), "l"(gmem_src), "r"(srcBytes));
}

__global__ void __launch_bounds__(256) gemm1_kernel(const float* __restrict__ A,
                                                    const float* __restrict__ W,
                                                    __nv_bfloat162* __restrict__ outb) {
    extern __shared__ float smem_[];
    float* sA = smem_;                     // [64][ASTRIDE] raw fp32 bits
    float* sB = smem_ + 64 * ASTRIDE;      // [128][BSTRIDE] W as-is [k][n]

    const int tid = threadIdx.x;           // 0..255
    const int wid = tid >> 5;
    const int lane = tid & 31;
    const int qr = lane >> 2;
    const int qc = lane & 3;
    const int warp_m = wid & 3;            // 4 m-warps, 16 rows each
    const int warp_n = wid >> 2;           // 2 n-warps, 32 cols each
    const int row0 = blockIdx.x * 64;

    // ---- stage A tile: 64 rows x 128 floats = 2048 x 16B, 8 per thread ----
#pragma unroll
    for (int it = 0; it < 8; it++) {
        int idx = it * 256 + tid;
        int row = idx >> 5;                // 32 chunks per row
        int c = idx & 31;
        int grow = row0 + row;
        int ok = (grow < NODES) ? 16 : 0;
        int srow = (grow < NODES) ? grow : (NODES - 1);
        cp_async16(&sA[row * ASTRIDE + c * 4], &A[(long)srow * INF + c * 4], ok);
    }
    // ---- stage W: 128 rows x 64 floats = 2048 x 16B, 8 per thread ----
#pragma unroll
    for (int it = 0; it < 8; it++) {
        int idx = it * 256 + tid;
        int row = idx >> 4;                // 16 chunks per row
        int c = idx & 15;
        cp_async16(&sB[row * BSTRIDE + c * 4], &W[(long)row * HF + c * 4], 16);
    }
    asm volatile("cp.async.commit_group;");
    asm volatile("cp.async.wait_group 0;");
    __syncthreads();

    const unsigned* sAu = (const unsigned*)sA;
    const unsigned* sBu = (const unsigned*)sB;

    float acc[4][4];
#pragma unroll
    for (int ni = 0; ni < 4; ni++)
#pragma unroll
        for (int j = 0; j < 4; j++) acc[ni][j] = 0.0f;

#pragma unroll
    for (int kk8 = 0; kk8 < 16; kk8++) {
        const int kk = kk8 * 8;
        unsigned a[4], b[4][2];
        int r = warp_m * 16 + qr;
        a[0] = sAu[r * ASTRIDE + kk + qc];
        a[1] = sAu[(r + 8) * ASTRIDE + kk + qc];
        a[2] = sAu[r * ASTRIDE + kk + qc + 4];
        a[3] = sAu[(r + 8) * ASTRIDE + kk + qc + 4];
#pragma unroll
        for (int ni = 0; ni < 4; ni++) {
            int n = warp_n * 32 + ni * 8 + qr;
            b[ni][0] = sBu[(kk + qc) * BSTRIDE + n];
            b[ni][1] = sBu[(kk + qc + 4) * BSTRIDE + n];
        }
#pragma unroll
        for (int ni = 0; ni < 4; ni++)
            mma_tf32(acc[ni], a, b[ni]);
    }

    // ---- epilogue: row-scale by ns, pack to bf16x2 ----
    int r0 = row0 + warp_m * 16 + qr;
    int r1 = r0 + 8;
    float ns0 = (r0 < NODES) ? g_ns[r0] : 0.0f;
    float ns1 = (r1 < NODES) ? g_ns[r1] : 0.0f;
#pragma unroll
    for (int ni = 0; ni < 4; ni++) {
        int col2 = (warp_n * 32 + ni * 8 + qc * 2) >> 1;
        if (r0 < NODES)
            outb[(long)r0 * (HF / 2) + col2] =
                __floats2bfloat162_rn(acc[ni][0] * ns0, acc[ni][1] * ns0);
        if (r1 < NODES)
            outb[(long)r1 * (HF / 2) + col2] =
                __floats2bfloat162_rn(acc[ni][2] * ns1, acc[ni][3] * ns1);
    }
}

// ---------------- fused layer: agg(tb_in) -> transform -> bf16 GEMM -> tb_out -
// Phase A: half-warp per node (16 lanes x 8B cover the 128B feature line);
//          each warp services 2 nodes concurrently -> halved serial depth.
// Phase B: 64x64 GEMM via mma.m16n8k16 bf16.
#define BPAD 72  // bf16 elems per row; 144B stride -> conflict-free frag loads

__device__ __forceinline__ void mma_bf16(float* d, const unsigned* a, const unsigned* b) {
    asm volatile(
        "mma.sync.aligned.m16n8k16.row.col.f32.bf16.bf16.f32 "
        "{%0,%1,%2,%3}, {%4,%5,%6,%7}, {%8,%9}, {%0,%1,%2,%3};\n"
        : "+f"(d[0]), "+f"(d[1]), "+f"(d[2]), "+f"(d[3])
        : "r"(a[0]), "r"(a[1]), "r"(a[2]), "r"(a[3]), "r"(b[0]), "r"(b[1]));
}

__global__ void fused_layer_kernel(const __nv_bfloat162* __restrict__ tb_in,
                                   const float* __restrict__ W,
                                   const float* __restrict__ bprev,
                                   __nv_bfloat162* __restrict__ tb_out) {
    __shared__ __nv_bfloat16 sA[64 * BPAD];  // [row][k]
    __shared__ __nv_bfloat16 sW[64 * BPAD];  // [n][k] (W transposed)

    const int tid = threadIdx.x;     // 0..255
    const int wid = tid >> 5;        // 0..7
    const int lane = tid & 31;
    const int row0 = blockIdx.x * 64;
    const uint2* tbu = (const uint2*)tb_in;  // [node][16] x 8B (4 bf16 each)

    // load W transposed -> sW[n][k]
#pragma unroll
    for (int it = 0; it < 16; it++) {
        int idx = it * 256 + tid;    // 4096
        int k = idx >> 6;
        int n = idx & 63;
        sW[n * BPAD + k] = __float2bfloat16(W[k * HF + n]);
    }

    // Phase A: half-warp per node, 4 node-pairs per warp
    const int half = lane >> 4;      // 0/1
    const int hl = lane & 15;        // 0..15 -> features 4*hl..4*hl+3
    const float4 bb = ((const float4*)bprev)[hl];
#pragma unroll 1
    for (int rp = 0; rp < 4; rp++) {
        int lrow = wid * 8 + rp * 2 + half;
        int row = row0 + lrow;
        float a0 = 0.f, a1 = 0.f, a2 = 0.f, a3 = 0.f;
        int j = 0, end = 0;
        if (row < NODES) { j = g_rowptr[row]; end = g_rowptr[row + 1]; }
        for (; j + 3 < end; j += 4) {
            int2 e0 = g_csr[j], e1 = g_csr[j + 1], e2 = g_csr[j + 2], e3 = g_csr[j + 3];
            uint2 v0 = tbu[(long)e0.x * 16 + hl];
            uint2 v1 = tbu[(long)e1.x * 16 + hl];
            uint2 v2 = tbu[(long)e2.x * 16 + hl];
            uint2 v3 = tbu[(long)e3.x * 16 + hl];
#define ACC_EDGE(e, v)                                                        \
            {                                                                 \
                float w = __int_as_float((e).y);                              \
                float2 lo = __bfloat1622float2(*(__nv_bfloat162*)&(v).x);     \
                float2 hi = __bfloat1622float2(*(__nv_bfloat162*)&(v).y);     \
                a0 = fmaf(lo.x, w, a0); a1 = fmaf(lo.y, w, a1);               \
                a2 = fmaf(hi.x, w, a2); a3 = fmaf(hi.y, w, a3);               \
            }
            ACC_EDGE(e0, v0) ACC_EDGE(e1, v1) ACC_EDGE(e2, v2) ACC_EDGE(e3, v3)
        }
        for (; j < end; j++) {
            int2 e0 = g_csr[j];
            uint2 v0 = tbu[(long)e0.x * 16 + hl];
            ACC_EDGE(e0, v0)
        }
#undef ACC_EDGE
        if (row < NODES) {
            float nd = g_nd[row];
            float ns = g_ns[row];
            a0 = fmaxf(fmaf(a0, nd, bb.x), 0.0f) * ns;
            a1 = fmaxf(fmaf(a1, nd, bb.y), 0.0f) * ns;
            a2 = fmaxf(fmaf(a2, nd, bb.z), 0.0f) * ns;
            a3 = fmaxf(fmaf(a3, nd, bb.w), 0.0f) * ns;
        }
        __nv_bfloat162 p0 = __floats2bfloat162_rn(a0, a1);
        __nv_bfloat162 p1 = __floats2bfloat162_rn(a2, a3);
        uint2 pk;
        pk.x = *(unsigned*)&p0;
        pk.y = *(unsigned*)&p1;
        *(uint2*)&sA[lrow * BPAD + 4 * hl] = pk;
    }
    __syncthreads();

    // Phase B: GEMM sA @ sW^T
    const int warp_m = wid & 3;
    const int warp_n = wid >> 2;
    const int qr = lane >> 2;
    const int qc = lane & 3;

    float acc[4][4];
#pragma unroll
    for (int ni = 0; ni < 4; ni++)
#pragma unroll
        for (int j = 0; j < 4; j++) acc[ni][j] = 0.0f;

#pragma unroll
    for (int ks = 0; ks < 4; ks++) {
        const int kk = ks * 16;
        unsigned a[4], b[4][2];
        int ra = warp_m * 16 + qr;
        a[0] = *(const unsigned*)&sA[ra * BPAD + kk + 2 * qc];
        a[1] = *(const unsigned*)&sA[(ra + 8) * BPAD + kk + 2 * qc];
        a[2] = *(const unsigned*)&sA[ra * BPAD + kk + 2 * qc + 8];
        a[3] = *(const unsigned*)&sA[(ra + 8) * BPAD + kk + 2 * qc + 8];
#pragma unroll
        for (int ni = 0; ni < 4; ni++) {
            int n = warp_n * 32 + ni * 8 + qr;
            b[ni][0] = *(const unsigned*)&sW[n * BPAD + kk + 2 * qc];
            b[ni][1] = *(const unsigned*)&sW[n * BPAD + kk + 2 * qc + 8];
        }
#pragma unroll
        for (int ni = 0; ni < 4; ni++)
            mma_bf16(acc[ni], a, b[ni]);
    }

    // epilogue
    int r0 = row0 + warp_m * 16 + qr;
    int r1 = r0 + 8;
#pragma unroll
    for (int ni = 0; ni < 4; ni++) {
        int col2 = (warp_n * 32 + ni * 8 + qc * 2) >> 1;
        if (r0 < NODES)
            tb_out[(long)r0 * (HF / 2) + col2] = __floats2bfloat162_rn(acc[ni][0], acc[ni][1]);
        if (r1 < NODES)
            tb_out[(long)r1 * (HF / 2) + col2] = __floats2bfloat162_rn(acc[ni][2], acc[ni][3]);
    }
}

// ---------------- layer-3 agg + activate: aggf = relu(agg*nd + b3) ------------
// half-warp per node: block of 256 covers 16 nodes.
__global__ void agg3_kernel(const __nv_bfloat162* __restrict__ tb,
                            const float* __restrict__ b3,
                            float* __restrict__ out) {
    int node = blockIdx.x * 16 + (threadIdx.x >> 4);
    if (node >= NODES) return;
    int hl = threadIdx.x & 15;
    const uint2* tbu = (const uint2*)tb;
    const float4 bb = ((const float4*)b3)[hl];
    int j = g_rowptr[node];
    int end = g_rowptr[node + 1];
    float a0 = 0.f, a1 = 0.f, a2 = 0.f, a3 = 0.f;
    for (; j + 3 < end; j += 4) {
        int2 e0 = g_csr[j], e1 = g_csr[j + 1], e2 = g_csr[j + 2], e3 = g_csr[j + 3];
        uint2 v0 = tbu[(long)e0.x * 16 + hl];
        uint2 v1 = tbu[(long)e1.x * 16 + hl];
        uint2 v2 = tbu[(long)e2.x * 16 + hl];
        uint2 v3 = tbu[(long)e3.x * 16 + hl];
#define ACC_EDGE(e, v)                                                        \
        {                                                                     \
            float w = __int_as_float((e).y);                                  \
            float2 lo = __bfloat1622float2(*(__nv_bfloat162*)&(v).x);         \
            float2 hi = __bfloat1622float2(*(__nv_bfloat162*)&(v).y);         \
            a0 = fmaf(lo.x, w, a0); a1 = fmaf(lo.y, w, a1);                   \
            a2 = fmaf(hi.x, w, a2); a3 = fmaf(hi.y, w, a3);                   \
        }
        ACC_EDGE(e0, v0) ACC_EDGE(e1, v1) ACC_EDGE(e2, v2) ACC_EDGE(e3, v3)
    }
    for (; j < end; j++) {
        int2 e0 = g_csr[j];
        uint2 v0 = tbu[(long)e0.x * 16 + hl];
        ACC_EDGE(e0, v0)
    }
#undef ACC_EDGE
    float nd = g_nd[node];
    float4 r;
    r.x = fmaxf(fmaf(a0, nd, bb.x), 0.0f);
    r.y = fmaxf(fmaf(a1, nd, bb.y), 0.0f);
    r.z = fmaxf(fmaf(a2, nd, bb.z), 0.0f);
    r.w = fmaxf(fmaf(a3, nd, bb.w), 0.0f);
    *(float4*)&out[(long)node * HF + 4 * hl] = r;
}

// ---------------- pool (mean per graph) + MLP head + sigmoid ------------------
__device__ __forceinline__ int lower_bound_dev(const int* __restrict__ a, int n, int key) {
    int lo = 0, hi = n;
    while (lo < hi) {
        int mid = (lo + hi) >> 1;
        if (a[mid] < key) lo = mid + 1; else hi = mid;
    }
    return lo;
}

__global__ void pool_mlp_kernel(const float* __restrict__ aggf,
                                const int* __restrict__ gid,
                                const float* __restrict__ Dw1, const float* __restrict__ Db1,
                                const float* __restrict__ Dw2, const float* __restrict__ Db2,
                                const float* __restrict__ Dw3, const float* __restrict__ Db3,
                                float* __restrict__ out) {
    int g = blockIdx.x;
    int t = threadIdx.x;  // 64 threads
    int start = lower_bound_dev(gid, NODES, g);
    int end = lower_bound_dev(gid, NODES, g + 1);

    float sum = 0.0f;
    for (int n = start; n < end; n++) sum += aggf[(long)n * HF + t];
    float cnt = fmaxf((float)(end - start), 1.0f);

    __shared__ float pooled[64];
    __shared__ float h1[16];
    __shared__ float h2[8];
    pooled[t] = sum / cnt;
    __syncthreads();

    if (t < 16) {
        float s = Db1[t];
#pragma unroll
        for (int k = 0; k < 64; k++) s = fmaf(pooled[k], Dw1[k * 16 + t], s);
        h1[t] = fmaxf(s, 0.0f);
    }
    __syncthreads();
    if (t < 8) {
        float s = Db2[t];
#pragma unroll
        for (int k = 0; k < 16; k++) s = fmaf(h1[k], Dw2[k * 8 + t], s);
        h2[t] = fmaxf(s, 0.0f);
    }
    __syncthreads();
    if (t == 0) {
        float s = Db3[0];
#pragma unroll
        for (int k = 0; k < 8; k++) s = fmaf(h2[k], Dw3[k], s);
        out[g] = 1.0f / (1.0f + expf(-s));
    }
}

// ---------------- launch ------------------------------------------------------
extern "C" void kernel_launch(void* const* d_in, const int* in_sizes, int n_in,
                              void* d_out, int out_size) {
    const float* x   = (const float*)d_in[0];
    const int*   src = (const int*)d_in[1];
    const int*   dst = (const int*)d_in[2];
    const float* ew  = (const float*)d_in[3];
    const int*   gid = (const int*)d_in[4];
    const float* W1  = (const float*)d_in[5];
    const float* b1  = (const float*)d_in[6];
    const float* W2  = (const float*)d_in[7];
    const float* b2  = (const float*)d_in[8];
    const float* W3  = (const float*)d_in[9];
    const float* b3  = (const float*)d_in[10];
    const float* Dw1 = (const float*)d_in[11];
    const float* Db1 = (const float*)d_in[12];
    const float* Dw2 = (const float*)d_in[13];
    const float* Db2 = (const float*)d_in[14];
    const float* Dw3 = (const float*)d_in[15];
    const float* Db3 = (const float*)d_in[16];
    float* out = (float*)d_out;

    __nv_bfloat162* tb_ptr; cudaGetSymbolAddress((void**)&tb_ptr, g_tb);
    float* aggf_ptr;        cudaGetSymbolAddress((void**)&aggf_ptr, g_aggf);

    const int NB = (NODES + 255) / 256;
    const int EB = (EDGES + 255) / 256;
    const int GB = (NODES + 63) / 64;    // 64-row tiles
    const int A3B = (NODES + 15) / 16;   // agg3 blocks (16 nodes each)

    // One-time setup: side stream + events + gemm1 dynamic smem opt-in.
    static cudaStream_t s2 = nullptr;
    static cudaEvent_t evA = nullptr, evB = nullptr;
    static bool inited = false;
    if (!inited) {
        cudaFuncSetAttribute(gemm1_kernel, cudaFuncAttributeMaxDynamicSharedMemorySize,
                             GEMM1_SMEM);
        if (cudaStreamCreateWithFlags(&s2, cudaStreamNonBlocking) != cudaSuccess) s2 = nullptr;
        if (s2) {
            if (cudaEventCreateWithFlags(&evA, cudaEventDisableTiming) != cudaSuccess ||
                cudaEventCreateWithFlags(&evB, cudaEventDisableTiming) != cudaSuccess) {
                s2 = nullptr;
            }
        }
        inited = true;
    }

    // 1-2: degree histogram (common dependency)
    zero_counts_kernel<<<NB, 256>>>();
    degree_kernel<<<EB, 256>>>(src, dst);

    if (s2) {
        // fork: CSR build on s2, norms+gemm1 on main — independent given degrees
        cudaEventRecord(evA, 0);
        cudaStreamWaitEvent(s2, evA, 0);

        norm_kernel<<<NB, 256>>>();
        gemm1_kernel<<<GB, 256, GEMM1_SMEM>>>(x, W1, tb_ptr);

        scan1_kernel<<<NBLK, SCAN_BLK, 0, s2>>>();
        scan2_kernel<<<1, 512, 0, s2>>>();
        scan3_kernel<<<NBLK, SCAN_BLK, 0, s2>>>();
        csr_fill_kernel<<<EB, 256, 0, s2>>>(src, dst, ew);
        cudaEventRecord(evB, s2);
        cudaStreamWaitEvent(0, evB, 0);
    } else {
        // sequential fallback
        norm_kernel<<<NB, 256>>>();
        gemm1_kernel<<<GB, 256, GEMM1_SMEM>>>(x, W1, tb_ptr);
        scan1_kernel<<<NBLK, SCAN_BLK>>>();
        scan2_kernel<<<1, 512>>>();
        scan3_kernel<<<NBLK, SCAN_BLK>>>();
        csr_fill_kernel<<<EB, 256>>>(src, dst, ew);
    }

    // fused agg+transform+GEMM for layers 2 and 3
    fused_layer_kernel<<<GB, 256>>>(tb_ptr, W2, b1, tb_ptr);
    fused_layer_kernel<<<GB, 256>>>(tb_ptr, W3, b2, tb_ptr);

    // layer-3 aggregation + activation
    agg3_kernel<<<A3B, 256>>>(tb_ptr, b3, aggf_ptr);

    // pool + MLP + sigmoid
    pool_mlp_kernel<<<GRAPHS, 64>>>(aggf_ptr, gid, Dw1, Db1, Dw2, Db2, Dw3, Db3, out);
}